// round 2
// baseline (speedup 1.0000x reference)
#include <cuda_runtime.h>
#include <cuda_bf16.h>
#include <math.h>

constexpr int NB  = 32;
constexpr int NC  = 128;
constexpr int NH  = 56, NWW = 56;
constexpr int NHW = NH * NWW;                 // 3136
constexpr int NCHW = NC * NHW;                // 401408
constexpr long long TAILOFF = (long long)NB * NCHW;   // 12845056
constexpr float THETA = 0.7f;

// ---------------- scratch (device globals; no runtime allocation) ----------------
__device__ float g_pooled[NB * NC];
__device__ int   g_top1[NB];
__device__ float g_k3cd[NC * NC * 9];
__device__ float g_k5[NC * NC * 25];
__device__ float g_y_srm[(size_t)NB * 384 * NHW];   // 154 MB
__device__ float g_t_srm[(size_t)NB * NCHW];
__device__ float g_y_hf [(size_t)NB * NCHW];
__device__ float g_t_hf [(size_t)NB * NCHW];
__device__ float g_psum[2][NC * 448];
__device__ float g_psq [2][NC * 448];
__device__ float2 g_bnp[2][NC];

// ---------------- f32x2 helpers ----------------
typedef unsigned long long F2;
__device__ __forceinline__ F2 f2pack(float lo, float hi) {
    F2 r; asm("mov.b64 %0, {%1,%2};" : "=l"(r) : "f"(lo), "f"(hi)); return r;
}
__device__ __forceinline__ F2 f2dup(float v) { return f2pack(v, v); }
__device__ __forceinline__ void f2fma(F2 &acc, F2 a, F2 b) {
    asm("fma.rn.f32x2 %0, %1, %2, %0;" : "+l"(acc) : "l"(a), "l"(b));
}
__device__ __forceinline__ void f2unpack(F2 v, float &lo, float &hi) {
    asm("mov.b64 {%0,%1}, %2;" : "=f"(lo), "=f"(hi) : "l"(v));
}

// ---------------- kernel 1: fold expert kernels ----------------
__global__ void k_prep(const float* __restrict__ cd, const float* __restrict__ bayar,
                       const float* __restrict__ shw) {
    int t = blockIdx.x * blockDim.x + threadIdx.x;
    if (t >= NC * NC) return;
    const float* cw = cd  + (long long)t * 9;
    const float* sw = shw + (long long)t * 9;
    float s = 0.f;
#pragma unroll
    for (int k = 0; k < 9; k++) s += cw[k];
    float* o3 = g_k3cd + (long long)t * 9;
#pragma unroll
    for (int k = 0; k < 9; k++) o3[k] = cw[k] + sw[k] - (k == 4 ? THETA * s : 0.f);

    const float* br = bayar + (long long)t * 24;
    float bs = 0.f;
#pragma unroll
    for (int k = 0; k < 24; k++) bs += br[k];
    float inv = 1.f / bs;
    float* o5 = g_k5 + (long long)t * 25;
#pragma unroll
    for (int k = 0; k < 25; k++) {
        float v;
        if (k < 12) v = br[k] * inv;
        else if (k == 12) v = -1.f;
        else v = br[k - 1] * inv;
        int r = k / 5, c = k % 5;
        if (r >= 1 && r <= 3 && c >= 1 && c <= 3) v += sw[(r - 1) * 3 + (c - 1)];
        o5[k] = v;
    }
}

// ---------------- kernel 2: spatial mean pool ----------------
__global__ void k_pool(const float* __restrict__ x) {
    int bc = blockIdx.x;
    const float* p = x + (long long)bc * NHW;
    float s = 0.f;
    for (int i = threadIdx.x; i < NHW; i += 128) s += p[i];
    __shared__ float sm[4];
#pragma unroll
    for (int o = 16; o > 0; o >>= 1) s += __shfl_down_sync(0xffffffff, s, o);
    if ((threadIdx.x & 31) == 0) sm[threadIdx.x >> 5] = s;
    __syncthreads();
    if (threadIdx.x == 0) g_pooled[bc] = (sm[0] + sm[1] + sm[2] + sm[3]) * (1.f / NHW);
}

// ---------------- kernel 3: gating + aux outputs ----------------
__global__ void k_gate(const float* __restrict__ Wg, float* __restrict__ out) {
    int b = threadIdx.x;
    if (b < NB) {
        float a0 = 0, a1 = 0, a2 = 0, a3 = 0;
        for (int c = 0; c < NC; c++) {
            float p = g_pooled[b * NC + c];
            a0 += p * Wg[c * 4 + 0]; a1 += p * Wg[c * 4 + 1];
            a2 += p * Wg[c * 4 + 2]; a3 += p * Wg[c * 4 + 3];
        }
        float l[4] = {a0, a1, a2, a3};
        int best = 0;
        for (int e = 1; e < 4; e++) if (l[e] > l[best]) best = e;  // first-max, matches jnp.argmax
        g_top1[b] = best;
        for (int e = 0; e < 4; e++) out[TAILOFF + 9 + b * 4 + e] = (e == best) ? 1.f : 0.f;
    }
    __syncwarp();
    if (threadIdx.x == 0) {
        float cnt[4] = {0, 0, 0, 0};
        for (int bb = 0; bb < NB; bb++) cnt[g_top1[bb]] += 1.f;
        float mean = (cnt[0] + cnt[1] + cnt[2] + cnt[3]) * 0.25f;
        float var = 0.f;
        for (int e = 0; e < 4; e++) { float d = cnt[e] - mean; var += d * d; }
        var *= 0.25f;
        out[TAILOFF] = var / (mean * mean + 1e-10f);
        for (int e = 0; e < 4; e++) { out[TAILOFF + 1 + e] = cnt[e]; out[TAILOFF + 5 + e] = cnt[e]; }
    }
}

// ---------------- kernel 4: SRM depthwise 5x5 (3 filters/channel) + hardtanh ----------------
__global__ void k_dw_srm(const float* __restrict__ x, const float* __restrict__ kern) {
    __shared__ float xt[60 * 60];
    __shared__ float kf[75];
    int b = blockIdx.x >> 7, ch = blockIdx.x & 127;
    const float* xs = x + (long long)(b * NC + ch) * NHW;
    for (int idx = threadIdx.x; idx < 3600; idx += 256) {
        int r = idx / 60, c = idx % 60, gr = r - 2, gc = c - 2;
        xt[idx] = (gr >= 0 && gr < 56 && gc >= 0 && gc < 56) ? xs[gr * 56 + gc] : 0.f;
    }
    if (threadIdx.x < 75) kf[threadIdx.x] = kern[ch * 75 + threadIdx.x];
    __syncthreads();
    float* yo = g_y_srm + (size_t)(b * 384 + 3 * ch) * NHW;
    for (int idx = threadIdx.x; idx < NHW; idx += 256) {
        int h = idx / 56, w = idx % 56;
        float s0 = 0, s1 = 0, s2 = 0;
#pragma unroll
        for (int dy = 0; dy < 5; dy++)
#pragma unroll
            for (int dx = 0; dx < 5; dx++) {
                float v = xt[(h + dy) * 60 + w + dx];
                s0 += kf[dy * 5 + dx] * v;
                s1 += kf[25 + dy * 5 + dx] * v;
                s2 += kf[50 + dy * 5 + dx] * v;
            }
        yo[idx]           = fminf(fmaxf(s0, -3.f), 3.f);
        yo[NHW + idx]     = fminf(fmaxf(s1, -3.f), 3.f);
        yo[2 * NHW + idx] = fminf(fmaxf(s2, -3.f), 3.f);
    }
}

// ---------------- kernel 5: HF depthwise 3x3 ----------------
__global__ void k_dw_hf(const float* __restrict__ x, const float* __restrict__ kern) {
    __shared__ float xt[58 * 58];
    __shared__ float kf[9];
    int b = blockIdx.x >> 7, ch = blockIdx.x & 127;
    const float* xs = x + (long long)(b * NC + ch) * NHW;
    for (int idx = threadIdx.x; idx < 58 * 58; idx += 256) {
        int r = idx / 58, c = idx % 58, gr = r - 1, gc = c - 1;
        xt[idx] = (gr >= 0 && gr < 56 && gc >= 0 && gc < 56) ? xs[gr * 56 + gc] : 0.f;
    }
    if (threadIdx.x < 9) kf[threadIdx.x] = kern[ch * 9 + threadIdx.x];
    __syncthreads();
    float* yo = g_y_hf + (size_t)(b * NC + ch) * NHW;
    for (int idx = threadIdx.x; idx < NHW; idx += 256) {
        int h = idx / 56, w = idx % 56;
        float s = 0.f;
#pragma unroll
        for (int dy = 0; dy < 3; dy++)
#pragma unroll
            for (int dx = 0; dx < 3; dx++) s += kf[dy * 3 + dx] * xt[(h + dy) * 58 + w + dx];
        yo[idx] = s;
    }
}

// ---------------- kernel 6: 1x1 conv (GEMM) + exact BN partial stats ----------------
// eid==2: srm (Cin=384), eid==3: hf (Cin=128). 448 threads = 32 ocg x 14 pixel-groups.
__global__ __launch_bounds__(448) void k_c1x1(const float* __restrict__ W, int Cin, int eid) {
    __shared__ __align__(16) float Ys[16 * 228];
    __shared__ __align__(16) float Wsm[128 * 17];
    const float *y; float *tout, *psum, *psq;
    if (eid == 2) { y = g_y_srm; tout = g_t_srm; psum = g_psum[0]; psq = g_psq[0]; }
    else          { y = g_y_hf;  tout = g_t_hf;  psum = g_psum[1]; psq = g_psq[1]; }

    int pt = blockIdx.x, b = blockIdx.y;
    int tid = threadIdx.x;
    int ocg = tid & 31, g = tid >> 5;
    int pbase = g * 16;
    F2 acc[4][8];
#pragma unroll
    for (int j = 0; j < 4; j++)
#pragma unroll
        for (int q = 0; q < 8; q++) acc[j][q] = 0ULL;

    const float* yb = y + (size_t)b * Cin * NHW + pt * 224;
    int chunks = Cin >> 4;
    for (int kc = 0; kc < chunks; kc++) {
        for (int idx = tid; idx < 16 * 224; idx += 448) {
            int i = idx / 224, p = idx % 224;
            Ys[i * 228 + p] = yb[(size_t)(kc * 16 + i) * NHW + p];
        }
        for (int idx = tid; idx < 128 * 16; idx += 448) {
            int o = idx >> 4, i = idx & 15;
            Wsm[o * 17 + i] = W[(long long)o * Cin + kc * 16 + i];
        }
        __syncthreads();
#pragma unroll
        for (int i = 0; i < 16; i++) {
            F2 yv[8];
            const float2* yr = (const float2*)(Ys + i * 228 + pbase);
#pragma unroll
            for (int q = 0; q < 8; q++) { float2 t2 = yr[q]; yv[q] = f2pack(t2.x, t2.y); }
#pragma unroll
            for (int j = 0; j < 4; j++) {
                F2 wv = f2dup(Wsm[(ocg + 32 * j) * 17 + i]);
#pragma unroll
                for (int q = 0; q < 8; q++) f2fma(acc[j][q], yv[q], wv);
            }
        }
        __syncthreads();
    }

    bool sel = (g_top1[b] == eid);
    float ls[4], lq[4];
#pragma unroll
    for (int j = 0; j < 4; j++) {
        int oc = ocg + 32 * j;
        float s = 0.f, qq = 0.f;
        float* tp = tout + (size_t)(b * NC + oc) * NHW + pt * 224 + pbase;
#pragma unroll
        for (int q = 0; q < 8; q++) {
            float lo, hi; f2unpack(acc[j][q], lo, hi);
            s += lo + hi; qq += lo * lo + hi * hi;
            if (sel) { float2 v; v.x = lo; v.y = hi; ((float2*)tp)[q] = v; }
        }
        ls[j] = s; lq[j] = qq;
    }
    // deterministic block-level reduce (alias Ys: 2*128*14 = 3584 <= 3648)
    float* redS = Ys;
    float* redQ = Ys + 128 * 14;
#pragma unroll
    for (int j = 0; j < 4; j++) {
        int oc = ocg + 32 * j;
        redS[oc * 14 + g] = ls[j];
        redQ[oc * 14 + g] = lq[j];
    }
    __syncthreads();
    if (tid < 128) {
        float s = 0.f, qq = 0.f;
        for (int g2 = 0; g2 < 14; g2++) { s += redS[tid * 14 + g2]; qq += redQ[tid * 14 + g2]; }
        psum[tid * 448 + b * 14 + pt] = s;
        psq [tid * 448 + b * 14 + pt] = qq;
    }
}

// ---------------- kernel 7: finish BN stats (double, deterministic) ----------------
__global__ void k_bn(const float* __restrict__ srm_g, const float* __restrict__ srm_b,
                     const float* __restrict__ hf_g,  const float* __restrict__ hf_b) {
    int e = blockIdx.x >> 7, oc = blockIdx.x & 127;
    __shared__ double sm0[64], sm1[64];
    double s = 0.0, q = 0.0;
    for (int i = threadIdx.x; i < 448; i += 64) {
        s += (double)g_psum[e][oc * 448 + i];
        q += (double)g_psq [e][oc * 448 + i];
    }
    sm0[threadIdx.x] = s; sm1[threadIdx.x] = q;
    __syncthreads();
    for (int o = 32; o > 0; o >>= 1) {
        if (threadIdx.x < o) { sm0[threadIdx.x] += sm0[threadIdx.x + o]; sm1[threadIdx.x] += sm1[threadIdx.x + o]; }
        __syncthreads();
    }
    if (threadIdx.x == 0) {
        double N = (double)NB * NHW;
        double mean = sm0[0] / N;
        double var  = sm1[0] / N - mean * mean;
        if (var < 0.0) var = 0.0;
        float gamma = e ? hf_g[oc] : srm_g[oc];
        float beta  = e ? hf_b[oc] : srm_b[oc];
        float scale = gamma * (float)(1.0 / sqrt(var + 1e-5));
        float shift = beta - (float)mean * scale;
        g_bnp[e][oc] = make_float2(scale, shift);
    }
}

// ---------------- kernel 8: routed main conv ----------------
// Block: (row tile of 4, oc tile of 32, b). 224 threads = 8 ocg x 28 spatial groups.
// Each thread: 4 oc x 8 cols via f32x2 accumulators.
template<int K>
__device__ __forceinline__ void conv_path(const float* __restrict__ xb, const float* __restrict__ W,
                                          int oc0, int row0, int rr, int c0, int ocg,
                                          float* Xs, float* Ws, F2 acc[4][4]) {
    const int PAD = K / 2;
    const int RIN = 4 + K - 1;
    const int CIN = 56 + K - 1;   // 58 or 60 (even -> float2 aligned)
    const int K2 = K * K;
    int tid = threadIdx.x;
    for (int ic = 0; ic < NC; ic++) {
        const float* xc = xb + (long long)ic * NHW;
        for (int idx = tid; idx < RIN * CIN; idx += 224) {
            int r = idx / CIN, c = idx % CIN;
            int gr = row0 - PAD + r, gc = c - PAD;
            Xs[r * CIN + c] = (gr >= 0 && gr < NH && gc >= 0 && gc < NWW) ? xc[gr * NWW + gc] : 0.f;
        }
        for (int idx = tid; idx < 32 * K2; idx += 224) {
            int o = idx / K2, t = idx % K2;
            Ws[o * K2 + t] = W[((long long)(oc0 + o) * NC + ic) * K2 + t];
        }
        __syncthreads();
#pragma unroll
        for (int dy = 0; dy < K; dy++) {
            float xr[K + 7];
            const float2* xp = (const float2*)(Xs + (rr + dy) * CIN + c0);
#pragma unroll
            for (int q = 0; q < (K + 7) / 2; q++) { float2 v = xp[q]; xr[2 * q] = v.x; xr[2 * q + 1] = v.y; }
#pragma unroll
            for (int dx = 0; dx < K; dx++) {
                F2 xv[4];
#pragma unroll
                for (int q = 0; q < 4; q++) xv[q] = f2pack(xr[dx + 2 * q], xr[dx + 2 * q + 1]);
#pragma unroll
                for (int j = 0; j < 4; j++) {
                    F2 wv = f2dup(Ws[(ocg + 8 * j) * K2 + dy * K + dx]);
#pragma unroll
                    for (int q = 0; q < 4; q++) f2fma(acc[j][q], xv[q], wv);
                }
            }
        }
        __syncthreads();
    }
}

__global__ __launch_bounds__(224, 2) void k_out(const float* __restrict__ x,
                                                const float* __restrict__ shw,
                                                float* __restrict__ out) {
    __shared__ __align__(16) float Xs[8 * 60];
    __shared__ __align__(16) float Ws[32 * 25];
    int rt = blockIdx.x, ot = blockIdx.y, b = blockIdx.z;
    int e = g_top1[b];
    int tid = threadIdx.x;
    int ocg = tid & 7, g = tid >> 3;
    int rr = g / 7, c0 = (g % 7) * 8;
    int row0 = rt * 4, oc0 = ot * 32;
    const float* xb = x + (long long)b * NCHW;

    F2 acc[4][4];
#pragma unroll
    for (int j = 0; j < 4; j++)
#pragma unroll
        for (int q = 0; q < 4; q++) acc[j][q] = 0ULL;

    if (e == 1)      conv_path<5>(xb, g_k5, oc0, row0, rr, c0, ocg, Xs, Ws, acc);
    else if (e == 0) conv_path<3>(xb, g_k3cd, oc0, row0, rr, c0, ocg, Xs, Ws, acc);
    else             conv_path<3>(xb, shw,   oc0, row0, rr, c0, ocg, Xs, Ws, acc);

    int row = row0 + rr;
    const float* tbase = (e == 2) ? g_t_srm : g_t_hf;
#pragma unroll
    for (int j = 0; j < 4; j++) {
        int oc = oc0 + ocg + 8 * j;
        float* op = out + (size_t)(b * NC + oc) * NHW + row * NWW + c0;
        float2 bnp = make_float2(0.f, 0.f);
        const float* tp = nullptr;
        if (e >= 2) {
            bnp = g_bnp[e - 2][oc];
            tp = tbase + (size_t)(b * NC + oc) * NHW + row * NWW + c0;
        }
#pragma unroll
        for (int q = 0; q < 4; q++) {
            float lo, hi; f2unpack(acc[j][q], lo, hi);
            if (e >= 2) {
                float2 tv = ((const float2*)tp)[q];
                lo += fmaxf(tv.x * bnp.x + bnp.y, 0.f);
                hi += fmaxf(tv.y * bnp.x + bnp.y, 0.f);
            }
            float2 v; v.x = lo; v.y = hi;
            ((float2*)op)[q] = v;
        }
    }
}

// ---------------- launcher ----------------
extern "C" void kernel_launch(void* const* d_in, const int* in_sizes, int n_in,
                              void* d_out, int out_size) {
    const float* x      = (const float*)d_in[0];
    const float* Wg     = (const float*)d_in[1];
    const float* cd_w   = (const float*)d_in[2];
    const float* bayar  = (const float*)d_in[3];
    const float* srm_k  = (const float*)d_in[4];
    const float* srm_ow = (const float*)d_in[5];
    const float* srm_g  = (const float*)d_in[6];
    const float* srm_b  = (const float*)d_in[7];
    const float* hf_k   = (const float*)d_in[8];
    const float* hf_ow  = (const float*)d_in[9];
    const float* hf_g   = (const float*)d_in[10];
    const float* hf_b   = (const float*)d_in[11];
    const float* shw    = (const float*)d_in[12];
    float* out = (float*)d_out;

    k_prep<<<(NC * NC + 127) / 128, 128>>>(cd_w, bayar, shw);
    k_pool<<<NB * NC, 128>>>(x);
    k_gate<<<1, 32>>>(Wg, out);
    k_dw_srm<<<NB * NC, 256>>>(x, srm_k);
    k_dw_hf<<<NB * NC, 256>>>(x, hf_k);
    k_c1x1<<<dim3(14, NB), 448>>>(srm_ow, 384, 2);
    k_c1x1<<<dim3(14, NB), 448>>>(hf_ow, 128, 3);
    k_bn<<<256, 64>>>(srm_g, srm_b, hf_g, hf_b);
    k_out<<<dim3(14, 4, NB), 224>>>(x, shw, out);
}

// round 5
// speedup vs baseline: 1.2724x; 1.2724x over previous
#include <cuda_runtime.h>
#include <cuda_bf16.h>
#include <math.h>

constexpr int NB  = 32;
constexpr int NC  = 128;
constexpr int NH  = 56, NWW = 56;
constexpr int NHW = NH * NWW;                 // 3136
constexpr int NCHW = NC * NHW;                // 401408
constexpr long long TAILOFF = (long long)NB * NCHW;   // 12845056
constexpr float THETA = 0.7f;

// ---------------- scratch ----------------
__device__ float g_pooled[NB * NC];
__device__ int   g_top1[NB];
__device__ float g_k3cd[NC * NC * 9];
__device__ float g_k5[NC * NC * 25];
__device__ float g_y_srm[(size_t)NB * 384 * NHW];
__device__ float g_t_srm[(size_t)NB * NCHW];
__device__ float g_y_hf [(size_t)NB * NCHW];
__device__ float g_t_hf [(size_t)NB * NCHW];
__device__ float g_psum[2][NC * 448];
__device__ float g_psq [2][NC * 448];
__device__ float2 g_bnp[2][NC];

// ---------------- f32x2 helpers ----------------
typedef unsigned long long F2;
__device__ __forceinline__ F2 f2pack(float lo, float hi) {
    F2 r; asm("mov.b64 %0, {%1,%2};" : "=l"(r) : "f"(lo), "f"(hi)); return r;
}
__device__ __forceinline__ F2 f2dup(float v) { return f2pack(v, v); }
__device__ __forceinline__ void f2fma(F2 &acc, F2 a, F2 b) {
    asm("fma.rn.f32x2 %0, %1, %2, %0;" : "+l"(acc) : "l"(a), "l"(b));
}
__device__ __forceinline__ void f2unpack(F2 v, float &lo, float &hi) {
    asm("mov.b64 {%0,%1}, %2;" : "=f"(lo), "=f"(hi) : "l"(v));
}

// ---------------- cp.async helpers ----------------
__device__ __forceinline__ unsigned s2u(const void* p) {
    return (unsigned)__cvta_generic_to_shared(p);
}
// src must always be a VALID address (clamped by caller); pred=false writes zeros.
__device__ __forceinline__ void cpa4(unsigned dst, const float* src, bool pred) {
    asm volatile("cp.async.ca.shared.global [%0], [%1], 4, %2;"
                 :: "r"(dst), "l"(src), "r"(pred ? 4 : 0));
}
__device__ __forceinline__ void cpa_commit() { asm volatile("cp.async.commit_group;"); }
template<int N>
__device__ __forceinline__ void cpa_wait() { asm volatile("cp.async.wait_group %0;" :: "n"(N)); }

// ---------------- kernel 1: fold expert kernels ----------------
__global__ void k_prep(const float* __restrict__ cd, const float* __restrict__ bayar,
                       const float* __restrict__ shw) {
    int t = blockIdx.x * blockDim.x + threadIdx.x;
    if (t >= NC * NC) return;
    const float* cw = cd  + (long long)t * 9;
    const float* sw = shw + (long long)t * 9;
    float s = 0.f;
#pragma unroll
    for (int k = 0; k < 9; k++) s += cw[k];
    float* o3 = g_k3cd + (long long)t * 9;
#pragma unroll
    for (int k = 0; k < 9; k++) o3[k] = cw[k] + sw[k] - (k == 4 ? THETA * s : 0.f);

    const float* br = bayar + (long long)t * 24;
    float bs = 0.f;
#pragma unroll
    for (int k = 0; k < 24; k++) bs += br[k];
    float inv = 1.f / bs;
    float* o5 = g_k5 + (long long)t * 25;
#pragma unroll
    for (int k = 0; k < 25; k++) {
        float v;
        if (k < 12) v = br[k] * inv;
        else if (k == 12) v = -1.f;
        else v = br[k - 1] * inv;
        int r = k / 5, c = k % 5;
        if (r >= 1 && r <= 3 && c >= 1 && c <= 3) v += sw[(r - 1) * 3 + (c - 1)];
        o5[k] = v;
    }
}

// ---------------- kernel 2: spatial mean pool ----------------
__global__ void k_pool(const float* __restrict__ x) {
    int bc = blockIdx.x;
    const float* p = x + (long long)bc * NHW;
    float s = 0.f;
    for (int i = threadIdx.x; i < NHW; i += 128) s += p[i];
    __shared__ float sm[4];
#pragma unroll
    for (int o = 16; o > 0; o >>= 1) s += __shfl_down_sync(0xffffffff, s, o);
    if ((threadIdx.x & 31) == 0) sm[threadIdx.x >> 5] = s;
    __syncthreads();
    if (threadIdx.x == 0) g_pooled[bc] = (sm[0] + sm[1] + sm[2] + sm[3]) * (1.f / NHW);
}

// ---------------- kernel 3: gating + aux outputs ----------------
__global__ void k_gate(const float* __restrict__ Wg, float* __restrict__ out) {
    int b = threadIdx.x;
    if (b < NB) {
        float a0 = 0, a1 = 0, a2 = 0, a3 = 0;
        for (int c = 0; c < NC; c++) {
            float p = g_pooled[b * NC + c];
            a0 += p * Wg[c * 4 + 0]; a1 += p * Wg[c * 4 + 1];
            a2 += p * Wg[c * 4 + 2]; a3 += p * Wg[c * 4 + 3];
        }
        float l[4] = {a0, a1, a2, a3};
        int best = 0;
        for (int e = 1; e < 4; e++) if (l[e] > l[best]) best = e;
        g_top1[b] = best;
        for (int e = 0; e < 4; e++) out[TAILOFF + 9 + b * 4 + e] = (e == best) ? 1.f : 0.f;
    }
    __syncwarp();
    if (threadIdx.x == 0) {
        float cnt[4] = {0, 0, 0, 0};
        for (int bb = 0; bb < NB; bb++) cnt[g_top1[bb]] += 1.f;
        float mean = (cnt[0] + cnt[1] + cnt[2] + cnt[3]) * 0.25f;
        float var = 0.f;
        for (int e = 0; e < 4; e++) { float d = cnt[e] - mean; var += d * d; }
        var *= 0.25f;
        out[TAILOFF] = var / (mean * mean + 1e-10f);
        for (int e = 0; e < 4; e++) { out[TAILOFF + 1 + e] = cnt[e]; out[TAILOFF + 5 + e] = cnt[e]; }
    }
}

// ---------------- kernel 4: SRM depthwise 5x5 + hardtanh ----------------
__global__ __launch_bounds__(256, 3) void k_dw_srm(const float* __restrict__ x,
                                                   const float* __restrict__ kern) {
    __shared__ float xt[60 * 60];
    __shared__ float kf[75];
    int b = blockIdx.x >> 7, ch = blockIdx.x & 127;
    const float* xs = x + (long long)(b * NC + ch) * NHW;
    for (int idx = threadIdx.x; idx < 3600; idx += 256) {
        int r = idx / 60, c = idx % 60, gr = r - 2, gc = c - 2;
        xt[idx] = (gr >= 0 && gr < 56 && gc >= 0 && gc < 56) ? xs[gr * 56 + gc] : 0.f;
    }
    if (threadIdx.x < 75) kf[threadIdx.x] = kern[ch * 75 + threadIdx.x];
    __syncthreads();
    float* yo = g_y_srm + (size_t)(b * 384 + 3 * ch) * NHW;
    for (int idx = threadIdx.x; idx < NHW; idx += 256) {
        int h = idx / 56, w = idx % 56;
        float s0 = 0, s1 = 0, s2 = 0;
#pragma unroll
        for (int dy = 0; dy < 5; dy++)
#pragma unroll
            for (int dx = 0; dx < 5; dx++) {
                float v = xt[(h + dy) * 60 + w + dx];
                s0 += kf[dy * 5 + dx] * v;
                s1 += kf[25 + dy * 5 + dx] * v;
                s2 += kf[50 + dy * 5 + dx] * v;
            }
        yo[idx]           = fminf(fmaxf(s0, -3.f), 3.f);
        yo[NHW + idx]     = fminf(fmaxf(s1, -3.f), 3.f);
        yo[2 * NHW + idx] = fminf(fmaxf(s2, -3.f), 3.f);
    }
}

// ---------------- kernel 5: HF depthwise 3x3 ----------------
__global__ __launch_bounds__(256, 4) void k_dw_hf(const float* __restrict__ x,
                                                  const float* __restrict__ kern) {
    __shared__ float xt[58 * 58];
    __shared__ float kf[9];
    int b = blockIdx.x >> 7, ch = blockIdx.x & 127;
    const float* xs = x + (long long)(b * NC + ch) * NHW;
    for (int idx = threadIdx.x; idx < 58 * 58; idx += 256) {
        int r = idx / 58, c = idx % 58, gr = r - 1, gc = c - 1;
        xt[idx] = (gr >= 0 && gr < 56 && gc >= 0 && gc < 56) ? xs[gr * 56 + gc] : 0.f;
    }
    if (threadIdx.x < 9) kf[threadIdx.x] = kern[ch * 9 + threadIdx.x];
    __syncthreads();
    float* yo = g_y_hf + (size_t)(b * NC + ch) * NHW;
    for (int idx = threadIdx.x; idx < NHW; idx += 256) {
        int h = idx / 56, w = idx % 56;
        float s = 0.f;
#pragma unroll
        for (int dy = 0; dy < 3; dy++)
#pragma unroll
            for (int dx = 0; dx < 3; dx++) s += kf[dy * 3 + dx] * xt[(h + dy) * 58 + w + dx];
        yo[idx] = s;
    }
}

// ---------------- kernel 6: 1x1 conv (GEMM) + BN partials, cp.async pipelined ----------------
constexpr int C1_YE = 16 * 224;          // 3584 y elements per chunk
constexpr int C1_WE = 128 * 16;          // 2048 w elements per chunk
constexpr int C1_YS = 16 * 228;          // y smem stride block
constexpr int C1_WS = 128 * 17;          // w smem block
constexpr int C1_SM = C1_YS + C1_WS;     // 5824 floats per buffer

__global__ __launch_bounds__(448) void k_c1x1(const float* __restrict__ W, int Cin, int eid) {
    __shared__ __align__(16) float Sm[2][C1_SM];
    const float *y; float *tout, *psum, *psq;
    if (eid == 2) { y = g_y_srm; tout = g_t_srm; psum = g_psum[0]; psq = g_psq[0]; }
    else          { y = g_y_hf;  tout = g_t_hf;  psum = g_psum[1]; psq = g_psq[1]; }

    int pt = blockIdx.x, b = blockIdx.y;
    int tid = threadIdx.x;
    int ocg = tid & 31, g = tid >> 5;
    int pbase = g * 16;
    F2 acc[4][8];
#pragma unroll
    for (int j = 0; j < 4; j++)
#pragma unroll
        for (int q = 0; q < 8; q++) acc[j][q] = 0ULL;

    const float* yb = y + (size_t)b * Cin * NHW + pt * 224;
    int chunks = Cin >> 4;

    auto prefetch = [&](int kc, float* Sb) {
#pragma unroll
        for (int k = 0; k < 13; k++) {
            int idx = tid + k * 448;
            if (idx < C1_YE) {
                int i = idx / 224, p = idx % 224;
                cpa4(s2u(Sb + i * 228 + p), yb + (size_t)(kc * 16 + i) * NHW + p, true);
            } else if (idx < C1_YE + C1_WE) {
                int i2 = idx - C1_YE;
                int o = i2 >> 4, i = i2 & 15;
                cpa4(s2u(Sb + C1_YS + o * 17 + i), W + (long long)o * Cin + kc * 16 + i, true);
            }
        }
    };

    prefetch(0, Sm[0]); cpa_commit();
    int buf = 0;
    for (int kc = 0; kc < chunks; kc++) {
        if (kc + 1 < chunks) { prefetch(kc + 1, Sm[buf ^ 1]); cpa_commit(); cpa_wait<1>(); }
        else cpa_wait<0>();
        __syncthreads();
        const float* Ys = Sm[buf];
        const float* Wsm = Sm[buf] + C1_YS;
#pragma unroll
        for (int i = 0; i < 16; i++) {
            F2 yv[8];
            const float2* yr = (const float2*)(Ys + i * 228 + pbase);
#pragma unroll
            for (int q = 0; q < 8; q++) { float2 t2 = yr[q]; yv[q] = f2pack(t2.x, t2.y); }
#pragma unroll
            for (int j = 0; j < 4; j++) {
                F2 wv = f2dup(Wsm[(ocg + 32 * j) * 17 + i]);
#pragma unroll
                for (int q = 0; q < 8; q++) f2fma(acc[j][q], yv[q], wv);
            }
        }
        __syncthreads();
        buf ^= 1;
    }

    bool sel = (g_top1[b] == eid);
    float ls[4], lq[4];
#pragma unroll
    for (int j = 0; j < 4; j++) {
        int oc = ocg + 32 * j;
        float s = 0.f, qq = 0.f;
        float* tp = tout + (size_t)(b * NC + oc) * NHW + pt * 224 + pbase;
#pragma unroll
        for (int q = 0; q < 8; q++) {
            float lo, hi; f2unpack(acc[j][q], lo, hi);
            s += lo + hi; qq += lo * lo + hi * hi;
            if (sel) { float2 v; v.x = lo; v.y = hi; ((float2*)tp)[q] = v; }
        }
        ls[j] = s; lq[j] = qq;
    }
    float* redS = Sm[0];
    float* redQ = Sm[0] + 128 * 14;
#pragma unroll
    for (int j = 0; j < 4; j++) {
        int oc = ocg + 32 * j;
        redS[oc * 14 + g] = ls[j];
        redQ[oc * 14 + g] = lq[j];
    }
    __syncthreads();
    if (tid < 128) {
        float s = 0.f, qq = 0.f;
        for (int g2 = 0; g2 < 14; g2++) { s += redS[tid * 14 + g2]; qq += redQ[tid * 14 + g2]; }
        psum[tid * 448 + b * 14 + pt] = s;
        psq [tid * 448 + b * 14 + pt] = qq;
    }
}

// ---------------- kernel 7: finish BN stats ----------------
__global__ void k_bn(const float* __restrict__ srm_g, const float* __restrict__ srm_b,
                     const float* __restrict__ hf_g,  const float* __restrict__ hf_b) {
    int e = blockIdx.x >> 7, oc = blockIdx.x & 127;
    __shared__ double sm0[64], sm1[64];
    double s = 0.0, q = 0.0;
    for (int i = threadIdx.x; i < 448; i += 64) {
        s += (double)g_psum[e][oc * 448 + i];
        q += (double)g_psq [e][oc * 448 + i];
    }
    sm0[threadIdx.x] = s; sm1[threadIdx.x] = q;
    __syncthreads();
    for (int o = 32; o > 0; o >>= 1) {
        if (threadIdx.x < o) { sm0[threadIdx.x] += sm0[threadIdx.x + o]; sm1[threadIdx.x] += sm1[threadIdx.x + o]; }
        __syncthreads();
    }
    if (threadIdx.x == 0) {
        double N = (double)NB * NHW;
        double mean = sm0[0] / N;
        double var  = sm1[0] / N - mean * mean;
        if (var < 0.0) var = 0.0;
        float gamma = e ? hf_g[oc] : srm_g[oc];
        float beta  = e ? hf_b[oc] : srm_b[oc];
        float scale = gamma * (float)(1.0 / sqrt(var + 1e-5));
        float shift = beta - (float)mean * scale;
        g_bnp[e][oc] = make_float2(scale, shift);
    }
}

// ---------------- kernel 8: routed main conv, all 128 oc per block, cp.async pipelined ----
constexpr int CONV_SMAX = 3680;   // max floats per buffer (K=5: 8*60 + 128*25)

template<int K>
__device__ __forceinline__ void conv_path(const float* __restrict__ xb, const float* __restrict__ W,
                                          int row0, float* S0, float* S1,
                                          F2 acc[8][4], int ocg, int rr, int c0) {
    const int PAD = K / 2;
    const int RIN = 4 + K - 1;
    const int CIN = 56 + K - 1;     // 58 or 60, even
    const int K2 = K * K;
    const int EX = RIN * CIN;
    const int E  = EX + 128 * K2;
    const int NIT = (E + 447) / 448;
    int tid = threadIdx.x;

    auto prefetch = [&](int ic, float* Sb) {
        const float* xc = xb + (size_t)ic * NHW;
#pragma unroll
        for (int k = 0; k < NIT; k++) {
            int idx = tid + k * 448;
            if (idx < EX) {
                int r = idx / CIN, c = idx % CIN;
                int gr = row0 - PAD + r, gc = c - PAD;
                bool ok = (gr >= 0 && gr < NH && gc >= 0 && gc < NWW);
                // clamp into-range so the formed address is always valid
                int grc = gr < 0 ? 0 : (gr > NH - 1 ? NH - 1 : gr);
                int gcc = gc < 0 ? 0 : (gc > NWW - 1 ? NWW - 1 : gc);
                cpa4(s2u(Sb + idx), xc + grc * NWW + gcc, ok);
            } else if (idx < E) {
                int i2 = idx - EX;                       // == o*K2 + t
                int o = i2 / K2, t = i2 % K2;
                cpa4(s2u(Sb + EX + i2), W + ((size_t)o * NC + ic) * K2 + t, true);
            }
        }
    };

    prefetch(0, S0); cpa_commit();
    float* Sb = S0; float* Sn = S1;
    for (int ic = 0; ic < NC; ic++) {
        if (ic + 1 < NC) { prefetch(ic + 1, Sn); cpa_commit(); cpa_wait<1>(); }
        else cpa_wait<0>();
        __syncthreads();
        const float* Xs = Sb;
        const float* Ws = Sb + EX;
#pragma unroll
        for (int dy = 0; dy < K; dy++) {
            float xr[K + 7];
            const float2* xp = (const float2*)(Xs + (rr + dy) * CIN + c0);
#pragma unroll
            for (int q = 0; q < (K + 7) / 2; q++) { float2 v = xp[q]; xr[2 * q] = v.x; xr[2 * q + 1] = v.y; }
#pragma unroll
            for (int dx = 0; dx < K; dx++) {
                F2 xv[4];
#pragma unroll
                for (int q = 0; q < 4; q++) xv[q] = f2pack(xr[dx + 2 * q], xr[dx + 2 * q + 1]);
#pragma unroll
                for (int j = 0; j < 8; j++) {
                    F2 wv = f2dup(Ws[(ocg + 16 * j) * K2 + dy * K + dx]);
#pragma unroll
                    for (int q = 0; q < 4; q++) f2fma(acc[j][q], xv[q], wv);
                }
            }
        }
        __syncthreads();
        float* t = Sb; Sb = Sn; Sn = t;
    }
}

__global__ __launch_bounds__(448, 1) void k_out(const float* __restrict__ x,
                                                const float* __restrict__ shw,
                                                float* __restrict__ out) {
    __shared__ __align__(16) float Sm[2][CONV_SMAX];
    int rt = blockIdx.x, b = blockIdx.y;
    int e = g_top1[b];
    int tid = threadIdx.x;
    int ocg = tid & 15, g = tid >> 4;     // ocg 0..15, g 0..27
    int rr = g / 7, c0 = (g % 7) * 8;
    int row0 = rt * 4;
    const float* xb = x + (size_t)b * NCHW;

    F2 acc[8][4];
#pragma unroll
    for (int j = 0; j < 8; j++)
#pragma unroll
        for (int q = 0; q < 4; q++) acc[j][q] = 0ULL;

    if (e == 1)      conv_path<5>(xb, g_k5,   row0, Sm[0], Sm[1], acc, ocg, rr, c0);
    else if (e == 0) conv_path<3>(xb, g_k3cd, row0, Sm[0], Sm[1], acc, ocg, rr, c0);
    else             conv_path<3>(xb, shw,    row0, Sm[0], Sm[1], acc, ocg, rr, c0);

    int row = row0 + rr;
    const float* tbase = (e == 2) ? g_t_srm : g_t_hf;
#pragma unroll
    for (int j = 0; j < 8; j++) {
        int oc = ocg + 16 * j;
        float* op = out + (size_t)(b * NC + oc) * NHW + row * NWW + c0;
        float2 bnp = make_float2(0.f, 0.f);
        const float* tp = nullptr;
        if (e >= 2) {
            bnp = g_bnp[e - 2][oc];
            tp = tbase + (size_t)(b * NC + oc) * NHW + row * NWW + c0;
        }
#pragma unroll
        for (int q = 0; q < 4; q++) {
            float lo, hi; f2unpack(acc[j][q], lo, hi);
            if (e >= 2) {
                float2 tv = ((const float2*)tp)[q];
                lo += fmaxf(tv.x * bnp.x + bnp.y, 0.f);
                hi += fmaxf(tv.y * bnp.x + bnp.y, 0.f);
            }
            float2 v; v.x = lo; v.y = hi;
            ((float2*)op)[q] = v;
        }
    }
}

// ---------------- launcher ----------------
extern "C" void kernel_launch(void* const* d_in, const int* in_sizes, int n_in,
                              void* d_out, int out_size) {
    const float* x      = (const float*)d_in[0];
    const float* Wg     = (const float*)d_in[1];
    const float* cd_w   = (const float*)d_in[2];
    const float* bayar  = (const float*)d_in[3];
    const float* srm_k  = (const float*)d_in[4];
    const float* srm_ow = (const float*)d_in[5];
    const float* srm_g  = (const float*)d_in[6];
    const float* srm_b  = (const float*)d_in[7];
    const float* hf_k   = (const float*)d_in[8];
    const float* hf_ow  = (const float*)d_in[9];
    const float* hf_g   = (const float*)d_in[10];
    const float* hf_b   = (const float*)d_in[11];
    const float* shw    = (const float*)d_in[12];
    float* out = (float*)d_out;

    k_prep<<<(NC * NC + 127) / 128, 128>>>(cd_w, bayar, shw);
    k_pool<<<NB * NC, 128>>>(x);
    k_gate<<<1, 32>>>(Wg, out);
    k_dw_srm<<<NB * NC, 256>>>(x, srm_k);
    k_dw_hf<<<NB * NC, 256>>>(x, hf_k);
    k_c1x1<<<dim3(14, NB), 448>>>(srm_ow, 384, 2);
    k_c1x1<<<dim3(14, NB), 448>>>(hf_ow, 128, 3);
    k_bn<<<256, 64>>>(srm_g, srm_b, hf_g, hf_b);
    k_out<<<dim3(14, NB), 448>>>(x, shw, out);
}

// round 6
// speedup vs baseline: 1.3629x; 1.0711x over previous
#include <cuda_runtime.h>
#include <cuda_bf16.h>
#include <cuda_fp16.h>
#include <math.h>

constexpr int NB  = 32;
constexpr int NC  = 128;
constexpr int NH  = 56, NWW = 56;
constexpr int NHW = NH * NWW;                 // 3136
constexpr int NCHW = NC * NHW;                // 401408
constexpr long long TAILOFF = (long long)NB * NCHW;   // 12845056
constexpr float THETA = 0.7f;

// ---------------- scratch ----------------
__device__ float  g_pooled[NB * NC];
__device__ int    g_top1[NB];
__device__ float  g_k3cd[NC * NC * 9];
__device__ float  g_k5[NC * NC * 25];
__device__ __half g_y_srm[(size_t)NB * 384 * NHW];   // fp16: 77 MB
__device__ float  g_t_srm[(size_t)NB * NCHW];
__device__ __half g_y_hf [(size_t)NB * NCHW];
__device__ float  g_t_hf [(size_t)NB * NCHW];
__device__ float  g_psum[2][NC * 896];
__device__ float  g_psq [2][NC * 896];
__device__ float2 g_bnp[2][NC];

// ---------------- f32x2 helpers ----------------
typedef unsigned long long F2;
__device__ __forceinline__ F2 f2pack(float lo, float hi) {
    F2 r; asm("mov.b64 %0, {%1,%2};" : "=l"(r) : "f"(lo), "f"(hi)); return r;
}
__device__ __forceinline__ F2 f2dup(float v) { return f2pack(v, v); }
__device__ __forceinline__ void f2fma(F2 &acc, F2 a, F2 b) {
    asm("fma.rn.f32x2 %0, %1, %2, %0;" : "+l"(acc) : "l"(a), "l"(b));
}
__device__ __forceinline__ void f2unpack(F2 v, float &lo, float &hi) {
    asm("mov.b64 {%0,%1}, %2;" : "=f"(lo), "=f"(hi) : "l"(v));
}

// ---------------- cp.async helpers ----------------
__device__ __forceinline__ unsigned s2u(const void* p) {
    return (unsigned)__cvta_generic_to_shared(p);
}
// src must be a VALID address (clamped by caller); pred=false writes zeros.
__device__ __forceinline__ void cpa4(unsigned dst, const void* src, bool pred) {
    asm volatile("cp.async.ca.shared.global [%0], [%1], 4, %2;"
                 :: "r"(dst), "l"(src), "r"(pred ? 4 : 0));
}
__device__ __forceinline__ void cpa_commit() { asm volatile("cp.async.commit_group;"); }
template<int N>
__device__ __forceinline__ void cpa_wait() { asm volatile("cp.async.wait_group %0;" :: "n"(N)); }

// ---------------- kernel 1: fold expert kernels ----------------
__global__ void k_prep(const float* __restrict__ cd, const float* __restrict__ bayar,
                       const float* __restrict__ shw) {
    int t = blockIdx.x * blockDim.x + threadIdx.x;
    if (t >= NC * NC) return;
    const float* cw = cd  + (long long)t * 9;
    const float* sw = shw + (long long)t * 9;
    float s = 0.f;
#pragma unroll
    for (int k = 0; k < 9; k++) s += cw[k];
    float* o3 = g_k3cd + (long long)t * 9;
#pragma unroll
    for (int k = 0; k < 9; k++) o3[k] = cw[k] + sw[k] - (k == 4 ? THETA * s : 0.f);

    const float* br = bayar + (long long)t * 24;
    float bs = 0.f;
#pragma unroll
    for (int k = 0; k < 24; k++) bs += br[k];
    float inv = 1.f / bs;
    float* o5 = g_k5 + (long long)t * 25;
#pragma unroll
    for (int k = 0; k < 25; k++) {
        float v;
        if (k < 12) v = br[k] * inv;
        else if (k == 12) v = -1.f;
        else v = br[k - 1] * inv;
        int r = k / 5, c = k % 5;
        if (r >= 1 && r <= 3 && c >= 1 && c <= 3) v += sw[(r - 1) * 3 + (c - 1)];
        o5[k] = v;
    }
}

// ---------------- kernel 2: spatial mean pool ----------------
__global__ void k_pool(const float* __restrict__ x) {
    int bc = blockIdx.x;
    const float* p = x + (long long)bc * NHW;
    float s = 0.f;
    for (int i = threadIdx.x; i < NHW; i += 128) s += p[i];
    __shared__ float sm[4];
#pragma unroll
    for (int o = 16; o > 0; o >>= 1) s += __shfl_down_sync(0xffffffff, s, o);
    if ((threadIdx.x & 31) == 0) sm[threadIdx.x >> 5] = s;
    __syncthreads();
    if (threadIdx.x == 0) g_pooled[bc] = (sm[0] + sm[1] + sm[2] + sm[3]) * (1.f / NHW);
}

// ---------------- kernel 3: gating + aux outputs ----------------
__global__ void k_gate(const float* __restrict__ Wg, float* __restrict__ out) {
    int b = threadIdx.x;
    if (b < NB) {
        float a0 = 0, a1 = 0, a2 = 0, a3 = 0;
        for (int c = 0; c < NC; c++) {
            float p = g_pooled[b * NC + c];
            a0 += p * Wg[c * 4 + 0]; a1 += p * Wg[c * 4 + 1];
            a2 += p * Wg[c * 4 + 2]; a3 += p * Wg[c * 4 + 3];
        }
        float l[4] = {a0, a1, a2, a3};
        int best = 0;
        for (int e = 1; e < 4; e++) if (l[e] > l[best]) best = e;
        g_top1[b] = best;
        for (int e = 0; e < 4; e++) out[TAILOFF + 9 + b * 4 + e] = (e == best) ? 1.f : 0.f;
    }
    __syncwarp();
    if (threadIdx.x == 0) {
        float cnt[4] = {0, 0, 0, 0};
        for (int bb = 0; bb < NB; bb++) cnt[g_top1[bb]] += 1.f;
        float mean = (cnt[0] + cnt[1] + cnt[2] + cnt[3]) * 0.25f;
        float var = 0.f;
        for (int e = 0; e < 4; e++) { float d = cnt[e] - mean; var += d * d; }
        var *= 0.25f;
        out[TAILOFF] = var / (mean * mean + 1e-10f);
        for (int e = 0; e < 4; e++) { out[TAILOFF + 1 + e] = cnt[e]; out[TAILOFF + 5 + e] = cnt[e]; }
    }
}

// ---------------- kernel 4: SRM depthwise 5x5 + hardtanh -> fp16 ----------------
__global__ __launch_bounds__(256, 3) void k_dw_srm(const float* __restrict__ x,
                                                   const float* __restrict__ kern) {
    __shared__ float xt[60 * 60];
    __shared__ float kf[75];
    int b = blockIdx.x >> 7, ch = blockIdx.x & 127;
    const float* xs = x + (long long)(b * NC + ch) * NHW;
    for (int idx = threadIdx.x; idx < 3600; idx += 256) {
        int r = idx / 60, c = idx % 60, gr = r - 2, gc = c - 2;
        xt[idx] = (gr >= 0 && gr < 56 && gc >= 0 && gc < 56) ? xs[gr * 56 + gc] : 0.f;
    }
    if (threadIdx.x < 75) kf[threadIdx.x] = kern[ch * 75 + threadIdx.x];
    __syncthreads();
    __half* yo = g_y_srm + (size_t)(b * 384 + 3 * ch) * NHW;
    for (int idx = threadIdx.x; idx < NHW; idx += 256) {
        int h = idx / 56, w = idx % 56;
        float s0 = 0, s1 = 0, s2 = 0;
#pragma unroll
        for (int dy = 0; dy < 5; dy++)
#pragma unroll
            for (int dx = 0; dx < 5; dx++) {
                float v = xt[(h + dy) * 60 + w + dx];
                s0 += kf[dy * 5 + dx] * v;
                s1 += kf[25 + dy * 5 + dx] * v;
                s2 += kf[50 + dy * 5 + dx] * v;
            }
        yo[idx]           = __float2half(fminf(fmaxf(s0, -3.f), 3.f));
        yo[NHW + idx]     = __float2half(fminf(fmaxf(s1, -3.f), 3.f));
        yo[2 * NHW + idx] = __float2half(fminf(fmaxf(s2, -3.f), 3.f));
    }
}

// ---------------- kernel 5: HF depthwise 3x3 -> fp16 ----------------
__global__ __launch_bounds__(256, 4) void k_dw_hf(const float* __restrict__ x,
                                                  const float* __restrict__ kern) {
    __shared__ float xt[58 * 58];
    __shared__ float kf[9];
    int b = blockIdx.x >> 7, ch = blockIdx.x & 127;
    const float* xs = x + (long long)(b * NC + ch) * NHW;
    for (int idx = threadIdx.x; idx < 58 * 58; idx += 256) {
        int r = idx / 58, c = idx % 58, gr = r - 1, gc = c - 1;
        xt[idx] = (gr >= 0 && gr < 56 && gc >= 0 && gc < 56) ? xs[gr * 56 + gc] : 0.f;
    }
    if (threadIdx.x < 9) kf[threadIdx.x] = kern[ch * 9 + threadIdx.x];
    __syncthreads();
    __half* yo = g_y_hf + (size_t)(b * NC + ch) * NHW;
    for (int idx = threadIdx.x; idx < NHW; idx += 256) {
        int h = idx / 56, w = idx % 56;
        float s = 0.f;
#pragma unroll
        for (int dy = 0; dy < 3; dy++)
#pragma unroll
            for (int dx = 0; dx < 3; dx++) s += kf[dy * 3 + dx] * xt[(h + dy) * 58 + w + dx];
        yo[idx] = __float2half(s);
    }
}

// ---------------- kernel 6: 1x1 conv (GEMM) + BN partials ----------------
// Block: 128 oc x 112 px (2 rows). 448 thr = 32 ocg x 14 px-groups of 8.
// acc[4][4] = 32 regs -> 2 blocks/SM. Ys in fp16. cp.async double buffered.
constexpr int C1_YOFF = 8704;                    // bytes: W (128*17 f32) first
constexpr int C1_BUF  = 12544;                   // 8704 + 16*58*4 (h2) padded

__global__ __launch_bounds__(448, 2) void k_c1x1(const float* __restrict__ W, int Cin, int eid) {
    __shared__ __align__(16) unsigned char Sm[2][C1_BUF];
    const __half *y; float *tout, *psum, *psq;
    if (eid == 2) { y = g_y_srm; tout = g_t_srm; psum = g_psum[0]; psq = g_psq[0]; }
    else          { y = g_y_hf;  tout = g_t_hf;  psum = g_psum[1]; psq = g_psq[1]; }

    int pt = blockIdx.x, b = blockIdx.y;          // pt 0..27 (112 px each)
    int tid = threadIdx.x;
    int ocg = tid & 31, g = tid >> 5;             // g 0..13
    F2 acc[4][4];
#pragma unroll
    for (int j = 0; j < 4; j++)
#pragma unroll
        for (int q = 0; q < 4; q++) acc[j][q] = 0ULL;

    const __half* yb = y + (size_t)b * Cin * NHW + pt * 112;
    int chunks = Cin >> 4;

    auto prefetch = [&](int kc, int buf) {
        float* Wb = (float*)Sm[buf];
        __half2* Yb2 = (__half2*)(Sm[buf] + C1_YOFF);
#pragma unroll
        for (int k = 0; k < 7; k++) {
            int idx = tid + k * 448;
            if (idx < 2048) {
                int o = idx >> 4, i = idx & 15;
                cpa4(s2u(Wb + o * 17 + i), W + (size_t)o * Cin + kc * 16 + i, true);
            } else if (idx < 2048 + 896) {
                int j2 = idx - 2048;
                int i = j2 / 56, p = j2 % 56;
                cpa4(s2u(Yb2 + i * 58 + p),
                     (const __half2*)(yb + (size_t)(kc * 16 + i) * NHW) + p, true);
            }
        }
    };

    prefetch(0, 0); cpa_commit();
    int buf = 0;
    for (int kc = 0; kc < chunks; kc++) {
        if (kc + 1 < chunks) { prefetch(kc + 1, buf ^ 1); cpa_commit(); cpa_wait<1>(); }
        else cpa_wait<0>();
        __syncthreads();
        const float* Wb = (const float*)Sm[buf];
        const __half2* Yb2 = (const __half2*)(Sm[buf] + C1_YOFF);
#pragma unroll
        for (int i = 0; i < 16; i++) {
            const __half2* yr = Yb2 + i * 58 + g * 4;
            F2 yv[4];
#pragma unroll
            for (int q = 0; q < 4; q++) {
                float2 f = __half22float2(yr[q]);
                yv[q] = f2pack(f.x, f.y);
            }
#pragma unroll
            for (int j = 0; j < 4; j++) {
                F2 wv = f2dup(Wb[(ocg + 32 * j) * 17 + i]);
#pragma unroll
                for (int q = 0; q < 4; q++) f2fma(acc[j][q], yv[q], wv);
            }
        }
        __syncthreads();
        buf ^= 1;
    }

    bool sel = (g_top1[b] == eid);
    float ls[4], lq[4];
#pragma unroll
    for (int j = 0; j < 4; j++) {
        int oc = ocg + 32 * j;
        float s = 0.f, qq = 0.f;
        float* tp = tout + (size_t)(b * NC + oc) * NHW + pt * 112 + g * 8;
#pragma unroll
        for (int q = 0; q < 4; q++) {
            float lo, hi; f2unpack(acc[j][q], lo, hi);
            s += lo + hi; qq += lo * lo + hi * hi;
            if (sel) { float2 v; v.x = lo; v.y = hi; ((float2*)tp)[q] = v; }
        }
        ls[j] = s; lq[j] = qq;
    }
    // deterministic block reduce (alias full smem as float scratch: 2*128*14 = 3584 f <= 6272 f)
    float* redS = (float*)Sm;
    float* redQ = redS + 128 * 14;
#pragma unroll
    for (int j = 0; j < 4; j++) {
        int oc = ocg + 32 * j;
        redS[oc * 14 + g] = ls[j];
        redQ[oc * 14 + g] = lq[j];
    }
    __syncthreads();
    if (tid < 128) {
        float s = 0.f, qq = 0.f;
        for (int g2 = 0; g2 < 14; g2++) { s += redS[tid * 14 + g2]; qq += redQ[tid * 14 + g2]; }
        psum[tid * 896 + b * 28 + pt] = s;
        psq [tid * 896 + b * 28 + pt] = qq;
    }
}

// ---------------- kernel 7: finish BN stats ----------------
__global__ void k_bn(const float* __restrict__ srm_g, const float* __restrict__ srm_b,
                     const float* __restrict__ hf_g,  const float* __restrict__ hf_b) {
    int e = blockIdx.x >> 7, oc = blockIdx.x & 127;
    __shared__ double sm0[64], sm1[64];
    double s = 0.0, q = 0.0;
    for (int i = threadIdx.x; i < 896; i += 64) {
        s += (double)g_psum[e][oc * 896 + i];
        q += (double)g_psq [e][oc * 896 + i];
    }
    sm0[threadIdx.x] = s; sm1[threadIdx.x] = q;
    __syncthreads();
    for (int o = 32; o > 0; o >>= 1) {
        if (threadIdx.x < o) { sm0[threadIdx.x] += sm0[threadIdx.x + o]; sm1[threadIdx.x] += sm1[threadIdx.x + o]; }
        __syncthreads();
    }
    if (threadIdx.x == 0) {
        double N = (double)NB * NHW;
        double mean = sm0[0] / N;
        double var  = sm1[0] / N - mean * mean;
        if (var < 0.0) var = 0.0;
        float gamma = e ? hf_g[oc] : srm_g[oc];
        float beta  = e ? hf_b[oc] : srm_b[oc];
        float scale = gamma * (float)(1.0 / sqrt(var + 1e-5));
        float shift = beta - (float)mean * scale;
        g_bnp[e][oc] = make_float2(scale, shift);
    }
}

// ---------------- kernel 8: routed main conv ----------------
// Block: 2 rows x 128 oc. 448 thr = 32 ocg x 14 groups (2 rows x 7 colgroups of 8).
// acc[4][4] = 32 regs -> 2 blocks/SM. cp.async double buffered over ic.
constexpr int CONV_SMAX = 3560;   // K=5: 6*60 + 128*25 floats

template<int K>
__device__ __forceinline__ void conv_path(const float* __restrict__ xb, const float* __restrict__ W,
                                          int row0, float* S0, float* S1,
                                          F2 acc[4][4], int ocg, int rr, int c0) {
    const int PAD = K / 2;
    const int RIN = 2 + K - 1;      // 4 or 6
    const int CIN = 56 + K - 1;     // 58 or 60
    const int K2 = K * K;
    const int EX = RIN * CIN;
    const int E  = EX + 128 * K2;
    const int NIT = (E + 447) / 448;
    int tid = threadIdx.x;

    auto prefetch = [&](int ic, float* Sb) {
        const float* xc = xb + (size_t)ic * NHW;
#pragma unroll
        for (int k = 0; k < NIT; k++) {
            int idx = tid + k * 448;
            if (idx < EX) {
                int r = idx / CIN, c = idx % CIN;
                int gr = row0 - PAD + r, gc = c - PAD;
                bool ok = (gr >= 0 && gr < NH && gc >= 0 && gc < NWW);
                int grc = gr < 0 ? 0 : (gr > NH - 1 ? NH - 1 : gr);
                int gcc = gc < 0 ? 0 : (gc > NWW - 1 ? NWW - 1 : gc);
                cpa4(s2u(Sb + idx), xc + grc * NWW + gcc, ok);
            } else if (idx < E) {
                int i2 = idx - EX;                       // == o*K2 + t
                int o = i2 / K2, t = i2 % K2;
                cpa4(s2u(Sb + EX + i2), W + ((size_t)o * NC + ic) * K2 + t, true);
            }
        }
    };

    prefetch(0, S0); cpa_commit();
    float* Sb = S0; float* Sn = S1;
    for (int ic = 0; ic < NC; ic++) {
        if (ic + 1 < NC) { prefetch(ic + 1, Sn); cpa_commit(); cpa_wait<1>(); }
        else cpa_wait<0>();
        __syncthreads();
        const float* Xs = Sb;
        const float* Ws = Sb + EX;
#pragma unroll
        for (int dy = 0; dy < K; dy++) {
            float xr[K + 7];
            const float2* xp = (const float2*)(Xs + (rr + dy) * CIN + c0);
#pragma unroll
            for (int q = 0; q < (K + 7) / 2; q++) { float2 v = xp[q]; xr[2 * q] = v.x; xr[2 * q + 1] = v.y; }
#pragma unroll
            for (int dx = 0; dx < K; dx++) {
                F2 xv[4];
#pragma unroll
                for (int q = 0; q < 4; q++) xv[q] = f2pack(xr[dx + 2 * q], xr[dx + 2 * q + 1]);
#pragma unroll
                for (int j = 0; j < 4; j++) {
                    F2 wv = f2dup(Ws[(ocg + 32 * j) * K2 + dy * K + dx]);
#pragma unroll
                    for (int q = 0; q < 4; q++) f2fma(acc[j][q], xv[q], wv);
                }
            }
        }
        __syncthreads();
        float* t = Sb; Sb = Sn; Sn = t;
    }
}

__global__ __launch_bounds__(448, 2) void k_out(const float* __restrict__ x,
                                                const float* __restrict__ shw,
                                                float* __restrict__ out) {
    __shared__ __align__(16) float Sm[2][CONV_SMAX];
    int rt = blockIdx.x, b = blockIdx.y;           // rt 0..27 (2 rows each)
    int e = g_top1[b];
    int tid = threadIdx.x;
    int ocg = tid & 31, g = tid >> 5;              // ocg 0..31, g 0..13
    int rr = g / 7, c0 = (g % 7) * 8;
    int row0 = rt * 2;
    const float* xb = x + (size_t)b * NCHW;

    F2 acc[4][4];
#pragma unroll
    for (int j = 0; j < 4; j++)
#pragma unroll
        for (int q = 0; q < 4; q++) acc[j][q] = 0ULL;

    if (e == 1)      conv_path<5>(xb, g_k5,   row0, Sm[0], Sm[1], acc, ocg, rr, c0);
    else if (e == 0) conv_path<3>(xb, g_k3cd, row0, Sm[0], Sm[1], acc, ocg, rr, c0);
    else             conv_path<3>(xb, shw,    row0, Sm[0], Sm[1], acc, ocg, rr, c0);

    int row = row0 + rr;
    const float* tbase = (e == 2) ? g_t_srm : g_t_hf;
#pragma unroll
    for (int j = 0; j < 4; j++) {
        int oc = ocg + 32 * j;
        float* op = out + (size_t)(b * NC + oc) * NHW + row * NWW + c0;
        float2 bnp = make_float2(0.f, 0.f);
        const float* tp = nullptr;
        if (e >= 2) {
            bnp = g_bnp[e - 2][oc];
            tp = tbase + (size_t)(b * NC + oc) * NHW + row * NWW + c0;
        }
#pragma unroll
        for (int q = 0; q < 4; q++) {
            float lo, hi; f2unpack(acc[j][q], lo, hi);
            if (e >= 2) {
                float2 tv = ((const float2*)tp)[q];
                lo += fmaxf(tv.x * bnp.x + bnp.y, 0.f);
                hi += fmaxf(tv.y * bnp.x + bnp.y, 0.f);
            }
            float2 v; v.x = lo; v.y = hi;
            ((float2*)op)[q] = v;
        }
    }
}

// ---------------- launcher ----------------
extern "C" void kernel_launch(void* const* d_in, const int* in_sizes, int n_in,
                              void* d_out, int out_size) {
    const float* x      = (const float*)d_in[0];
    const float* Wg     = (const float*)d_in[1];
    const float* cd_w   = (const float*)d_in[2];
    const float* bayar  = (const float*)d_in[3];
    const float* srm_k  = (const float*)d_in[4];
    const float* srm_ow = (const float*)d_in[5];
    const float* srm_g  = (const float*)d_in[6];
    const float* srm_b  = (const float*)d_in[7];
    const float* hf_k   = (const float*)d_in[8];
    const float* hf_ow  = (const float*)d_in[9];
    const float* hf_g   = (const float*)d_in[10];
    const float* hf_b   = (const float*)d_in[11];
    const float* shw    = (const float*)d_in[12];
    float* out = (float*)d_out;

    k_prep<<<(NC * NC + 127) / 128, 128>>>(cd_w, bayar, shw);
    k_pool<<<NB * NC, 128>>>(x);
    k_gate<<<1, 32>>>(Wg, out);
    k_dw_srm<<<NB * NC, 256>>>(x, srm_k);
    k_dw_hf<<<NB * NC, 256>>>(x, hf_k);
    k_c1x1<<<dim3(28, NB), 448>>>(srm_ow, 384, 2);
    k_c1x1<<<dim3(28, NB), 448>>>(hf_ow, 128, 3);
    k_bn<<<256, 64>>>(srm_g, srm_b, hf_g, hf_b);
    k_out<<<dim3(28, NB), 448>>>(x, shw, out);
}

// round 7
// speedup vs baseline: 2.7905x; 2.0475x over previous
#include <cuda_runtime.h>
#include <cuda_bf16.h>
#include <cuda_fp16.h>
#include <math.h>

constexpr int NB  = 32;
constexpr int NC  = 128;
constexpr int NH  = 56, NWW = 56;
constexpr int NHW = NH * NWW;                 // 3136
constexpr int NCHW = NC * NHW;                // 401408
constexpr long long TAILOFF = (long long)NB * NCHW;   // 12845056
constexpr float THETA = 0.7f;

// ---------------- scratch ----------------
__device__ float  g_pooled[NB * NC];
__device__ int    g_top1[NB];
__device__ __half g_xh[(size_t)NB * NHW * NC];       // channels-last fp16 x (25.7MB)
__device__ __half g_wh3cd[9 * NC * NC];              // [tap][oc][ic]
__device__ __half g_wh3sh[9 * NC * NC];
__device__ __half g_wh5[25 * NC * NC];
__device__ __half g_y_srm[(size_t)NB * 384 * NHW];
__device__ float  g_t_srm[(size_t)NB * NCHW];
__device__ __half g_y_hf [(size_t)NB * NCHW];
__device__ float  g_t_hf [(size_t)NB * NCHW];
__device__ float  g_psum[2][NC * 896];
__device__ float  g_psq [2][NC * 896];
__device__ float2 g_bnp[2][NC];

// ---------------- f32x2 helpers ----------------
typedef unsigned long long F2;
__device__ __forceinline__ F2 f2pack(float lo, float hi) {
    F2 r; asm("mov.b64 %0, {%1,%2};" : "=l"(r) : "f"(lo), "f"(hi)); return r;
}
__device__ __forceinline__ F2 f2dup(float v) { return f2pack(v, v); }
__device__ __forceinline__ void f2fma(F2 &acc, F2 a, F2 b) {
    asm("fma.rn.f32x2 %0, %1, %2, %0;" : "+l"(acc) : "l"(a), "l"(b));
}
__device__ __forceinline__ void f2unpack(F2 v, float &lo, float &hi) {
    asm("mov.b64 {%0,%1}, %2;" : "=f"(lo), "=f"(hi) : "l"(v));
}

// ---------------- cp.async helpers ----------------
__device__ __forceinline__ unsigned s2u(const void* p) {
    return (unsigned)__cvta_generic_to_shared(p);
}
__device__ __forceinline__ void cpa4(unsigned dst, const void* src, bool pred) {
    asm volatile("cp.async.ca.shared.global [%0], [%1], 4, %2;"
                 :: "r"(dst), "l"(src), "r"(pred ? 4 : 0));
}
__device__ __forceinline__ void cpa16(unsigned dst, const void* src, bool pred) {
    asm volatile("cp.async.cg.shared.global [%0], [%1], 16, %2;"
                 :: "r"(dst), "l"(src), "r"(pred ? 16 : 0));
}
__device__ __forceinline__ void cpa_commit() { asm volatile("cp.async.commit_group;"); }
template<int N>
__device__ __forceinline__ void cpa_wait() { asm volatile("cp.async.wait_group %0;" :: "n"(N)); }

// ---------------- mma m16n8k16 fp16->fp32 ----------------
__device__ __forceinline__ void mma16816(float c[4], const unsigned a[4], unsigned b0, unsigned b1) {
    asm volatile("mma.sync.aligned.m16n8k16.row.col.f32.f16.f16.f32 "
                 "{%0,%1,%2,%3}, {%4,%5,%6,%7}, {%8,%9}, {%0,%1,%2,%3};"
                 : "+f"(c[0]), "+f"(c[1]), "+f"(c[2]), "+f"(c[3])
                 : "r"(a[0]), "r"(a[1]), "r"(a[2]), "r"(a[3]), "r"(b0), "r"(b1));
}

// ---------------- kernel 1: fold expert kernels -> fp16 [tap][oc][ic] ----------------
__global__ void k_prep(const float* __restrict__ cd, const float* __restrict__ bayar,
                       const float* __restrict__ shw) {
    int t = blockIdx.x * blockDim.x + threadIdx.x;
    if (t >= NC * NC) return;
    const float* cw = cd  + (long long)t * 9;
    const float* sw = shw + (long long)t * 9;
    float s = 0.f;
#pragma unroll
    for (int k = 0; k < 9; k++) s += cw[k];
#pragma unroll
    for (int k = 0; k < 9; k++) {
        float v = cw[k] + sw[k] - (k == 4 ? THETA * s : 0.f);
        g_wh3cd[k * (NC * NC) + t] = __float2half(v);
        g_wh3sh[k * (NC * NC) + t] = __float2half(sw[k]);
    }
    const float* br = bayar + (long long)t * 24;
    float bs = 0.f;
#pragma unroll
    for (int k = 0; k < 24; k++) bs += br[k];
    float inv = 1.f / bs;
#pragma unroll
    for (int k = 0; k < 25; k++) {
        float v;
        if (k < 12) v = br[k] * inv;
        else if (k == 12) v = -1.f;
        else v = br[k - 1] * inv;
        int r = k / 5, c = k % 5;
        if (r >= 1 && r <= 3 && c >= 1 && c <= 3) v += sw[(r - 1) * 3 + (c - 1)];
        g_wh5[k * (NC * NC) + t] = __float2half(v);
    }
}

// ---------------- kernel 1b: x -> channels-last fp16 ----------------
__global__ void k_xh(const float* __restrict__ x) {
    __shared__ float sm[128][57];
    int row = blockIdx.x, b = blockIdx.y;
    const float* xp = x + (size_t)b * NCHW + row * 56;
    for (int idx = threadIdx.x; idx < 128 * 56; idx += 256) {
        int ic = idx / 56, c = idx % 56;
        sm[ic][c] = xp[(size_t)ic * NHW + c];
    }
    __syncthreads();
    __half2* outp = (__half2*)(g_xh + ((size_t)b * NHW + row * 56) * NC);
    for (int idx = threadIdx.x; idx < 56 * 64; idx += 256) {
        int c = idx / 64, icp = idx % 64;
        outp[c * 64 + icp] = __floats2half2_rn(sm[icp * 2][c], sm[icp * 2 + 1][c]);
    }
}

// ---------------- kernel 2: spatial mean pool ----------------
__global__ void k_pool(const float* __restrict__ x) {
    int bc = blockIdx.x;
    const float* p = x + (long long)bc * NHW;
    float s = 0.f;
    for (int i = threadIdx.x; i < NHW; i += 128) s += p[i];
    __shared__ float sm[4];
#pragma unroll
    for (int o = 16; o > 0; o >>= 1) s += __shfl_down_sync(0xffffffff, s, o);
    if ((threadIdx.x & 31) == 0) sm[threadIdx.x >> 5] = s;
    __syncthreads();
    if (threadIdx.x == 0) g_pooled[bc] = (sm[0] + sm[1] + sm[2] + sm[3]) * (1.f / NHW);
}

// ---------------- kernel 3: gating + aux outputs ----------------
__global__ void k_gate(const float* __restrict__ Wg, float* __restrict__ out) {
    int b = threadIdx.x;
    if (b < NB) {
        float a0 = 0, a1 = 0, a2 = 0, a3 = 0;
        for (int c = 0; c < NC; c++) {
            float p = g_pooled[b * NC + c];
            a0 += p * Wg[c * 4 + 0]; a1 += p * Wg[c * 4 + 1];
            a2 += p * Wg[c * 4 + 2]; a3 += p * Wg[c * 4 + 3];
        }
        float l[4] = {a0, a1, a2, a3};
        int best = 0;
        for (int e = 1; e < 4; e++) if (l[e] > l[best]) best = e;
        g_top1[b] = best;
        for (int e = 0; e < 4; e++) out[TAILOFF + 9 + b * 4 + e] = (e == best) ? 1.f : 0.f;
    }
    __syncwarp();
    if (threadIdx.x == 0) {
        float cnt[4] = {0, 0, 0, 0};
        for (int bb = 0; bb < NB; bb++) cnt[g_top1[bb]] += 1.f;
        float mean = (cnt[0] + cnt[1] + cnt[2] + cnt[3]) * 0.25f;
        float var = 0.f;
        for (int e = 0; e < 4; e++) { float d = cnt[e] - mean; var += d * d; }
        var *= 0.25f;
        out[TAILOFF] = var / (mean * mean + 1e-10f);
        for (int e = 0; e < 4; e++) { out[TAILOFF + 1 + e] = cnt[e]; out[TAILOFF + 5 + e] = cnt[e]; }
    }
}

// ---------------- kernel 4: SRM depthwise 5x5 + hardtanh -> fp16 ----------------
__global__ __launch_bounds__(256, 3) void k_dw_srm(const float* __restrict__ x,
                                                   const float* __restrict__ kern) {
    __shared__ float xt[60 * 60];
    __shared__ float kf[75];
    int b = blockIdx.x >> 7, ch = blockIdx.x & 127;
    const float* xs = x + (long long)(b * NC + ch) * NHW;
    for (int idx = threadIdx.x; idx < 3600; idx += 256) {
        int r = idx / 60, c = idx % 60, gr = r - 2, gc = c - 2;
        xt[idx] = (gr >= 0 && gr < 56 && gc >= 0 && gc < 56) ? xs[gr * 56 + gc] : 0.f;
    }
    if (threadIdx.x < 75) kf[threadIdx.x] = kern[ch * 75 + threadIdx.x];
    __syncthreads();
    __half* yo = g_y_srm + (size_t)(b * 384 + 3 * ch) * NHW;
    for (int idx = threadIdx.x; idx < NHW; idx += 256) {
        int h = idx / 56, w = idx % 56;
        float s0 = 0, s1 = 0, s2 = 0;
#pragma unroll
        for (int dy = 0; dy < 5; dy++)
#pragma unroll
            for (int dx = 0; dx < 5; dx++) {
                float v = xt[(h + dy) * 60 + w + dx];
                s0 += kf[dy * 5 + dx] * v;
                s1 += kf[25 + dy * 5 + dx] * v;
                s2 += kf[50 + dy * 5 + dx] * v;
            }
        yo[idx]           = __float2half(fminf(fmaxf(s0, -3.f), 3.f));
        yo[NHW + idx]     = __float2half(fminf(fmaxf(s1, -3.f), 3.f));
        yo[2 * NHW + idx] = __float2half(fminf(fmaxf(s2, -3.f), 3.f));
    }
}

// ---------------- kernel 5: HF depthwise 3x3 -> fp16 ----------------
__global__ __launch_bounds__(256, 4) void k_dw_hf(const float* __restrict__ x,
                                                  const float* __restrict__ kern) {
    __shared__ float xt[58 * 58];
    __shared__ float kf[9];
    int b = blockIdx.x >> 7, ch = blockIdx.x & 127;
    const float* xs = x + (long long)(b * NC + ch) * NHW;
    for (int idx = threadIdx.x; idx < 58 * 58; idx += 256) {
        int r = idx / 58, c = idx % 58, gr = r - 1, gc = c - 1;
        xt[idx] = (gr >= 0 && gr < 56 && gc >= 0 && gc < 56) ? xs[gr * 56 + gc] : 0.f;
    }
    if (threadIdx.x < 9) kf[threadIdx.x] = kern[ch * 9 + threadIdx.x];
    __syncthreads();
    __half* yo = g_y_hf + (size_t)(b * NC + ch) * NHW;
    for (int idx = threadIdx.x; idx < NHW; idx += 256) {
        int h = idx / 56, w = idx % 56;
        float s = 0.f;
#pragma unroll
        for (int dy = 0; dy < 3; dy++)
#pragma unroll
            for (int dx = 0; dx < 3; dx++) s += kf[dy * 3 + dx] * xt[(h + dy) * 58 + w + dx];
        yo[idx] = __float2half(s);
    }
}

// ---------------- kernel 6: 1x1 conv (GEMM) + BN partials (f32x2, unchanged) ------------
constexpr int C1_YOFF = 8704;
constexpr int C1_BUF  = 12544;

__global__ __launch_bounds__(448, 2) void k_c1x1(const float* __restrict__ W, int Cin, int eid) {
    __shared__ __align__(16) unsigned char Sm[2][C1_BUF];
    const __half *y; float *tout, *psum, *psq;
    if (eid == 2) { y = g_y_srm; tout = g_t_srm; psum = g_psum[0]; psq = g_psq[0]; }
    else          { y = g_y_hf;  tout = g_t_hf;  psum = g_psum[1]; psq = g_psq[1]; }

    int pt = blockIdx.x, b = blockIdx.y;
    int tid = threadIdx.x;
    int ocg = tid & 31, g = tid >> 5;
    F2 acc[4][4];
#pragma unroll
    for (int j = 0; j < 4; j++)
#pragma unroll
        for (int q = 0; q < 4; q++) acc[j][q] = 0ULL;

    const __half* yb = y + (size_t)b * Cin * NHW + pt * 112;
    int chunks = Cin >> 4;

    auto prefetch = [&](int kc, int buf) {
        float* Wb = (float*)Sm[buf];
        __half2* Yb2 = (__half2*)(Sm[buf] + C1_YOFF);
#pragma unroll
        for (int k = 0; k < 7; k++) {
            int idx = tid + k * 448;
            if (idx < 2048) {
                int o = idx >> 4, i = idx & 15;
                cpa4(s2u(Wb + o * 17 + i), W + (size_t)o * Cin + kc * 16 + i, true);
            } else if (idx < 2048 + 896) {
                int j2 = idx - 2048;
                int i = j2 / 56, p = j2 % 56;
                cpa4(s2u(Yb2 + i * 58 + p),
                     (const __half2*)(yb + (size_t)(kc * 16 + i) * NHW) + p, true);
            }
        }
    };

    prefetch(0, 0); cpa_commit();
    int buf = 0;
    for (int kc = 0; kc < chunks; kc++) {
        if (kc + 1 < chunks) { prefetch(kc + 1, buf ^ 1); cpa_commit(); cpa_wait<1>(); }
        else cpa_wait<0>();
        __syncthreads();
        const float* Wb = (const float*)Sm[buf];
        const __half2* Yb2 = (const __half2*)(Sm[buf] + C1_YOFF);
#pragma unroll
        for (int i = 0; i < 16; i++) {
            const __half2* yr = Yb2 + i * 58 + g * 4;
            F2 yv[4];
#pragma unroll
            for (int q = 0; q < 4; q++) {
                float2 f = __half22float2(yr[q]);
                yv[q] = f2pack(f.x, f.y);
            }
#pragma unroll
            for (int j = 0; j < 4; j++) {
                F2 wv = f2dup(Wb[(ocg + 32 * j) * 17 + i]);
#pragma unroll
                for (int q = 0; q < 4; q++) f2fma(acc[j][q], yv[q], wv);
            }
        }
        __syncthreads();
        buf ^= 1;
    }

    bool sel = (g_top1[b] == eid);
    float ls[4], lq[4];
#pragma unroll
    for (int j = 0; j < 4; j++) {
        int oc = ocg + 32 * j;
        float s = 0.f, qq = 0.f;
        float* tp = tout + (size_t)(b * NC + oc) * NHW + pt * 112 + g * 8;
#pragma unroll
        for (int q = 0; q < 4; q++) {
            float lo, hi; f2unpack(acc[j][q], lo, hi);
            s += lo + hi; qq += lo * lo + hi * hi;
            if (sel) { float2 v; v.x = lo; v.y = hi; ((float2*)tp)[q] = v; }
        }
        ls[j] = s; lq[j] = qq;
    }
    float* redS = (float*)Sm;
    float* redQ = redS + 128 * 14;
#pragma unroll
    for (int j = 0; j < 4; j++) {
        int oc = ocg + 32 * j;
        redS[oc * 14 + g] = ls[j];
        redQ[oc * 14 + g] = lq[j];
    }
    __syncthreads();
    if (tid < 128) {
        float s = 0.f, qq = 0.f;
        for (int g2 = 0; g2 < 14; g2++) { s += redS[tid * 14 + g2]; qq += redQ[tid * 14 + g2]; }
        psum[tid * 896 + b * 28 + pt] = s;
        psq [tid * 896 + b * 28 + pt] = qq;
    }
}

// ---------------- kernel 7: finish BN stats ----------------
__global__ void k_bn(const float* __restrict__ srm_g, const float* __restrict__ srm_b,
                     const float* __restrict__ hf_g,  const float* __restrict__ hf_b) {
    int e = blockIdx.x >> 7, oc = blockIdx.x & 127;
    __shared__ double sm0[64], sm1[64];
    double s = 0.0, q = 0.0;
    for (int i = threadIdx.x; i < 896; i += 64) {
        s += (double)g_psum[e][oc * 896 + i];
        q += (double)g_psq [e][oc * 896 + i];
    }
    sm0[threadIdx.x] = s; sm1[threadIdx.x] = q;
    __syncthreads();
    for (int o = 32; o > 0; o >>= 1) {
        if (threadIdx.x < o) { sm0[threadIdx.x] += sm0[threadIdx.x + o]; sm1[threadIdx.x] += sm1[threadIdx.x + o]; }
        __syncthreads();
    }
    if (threadIdx.x == 0) {
        double N = (double)NB * NHW;
        double mean = sm0[0] / N;
        double var  = sm1[0] / N - mean * mean;
        if (var < 0.0) var = 0.0;
        float gamma = e ? hf_g[oc] : srm_g[oc];
        float beta  = e ? hf_b[oc] : srm_b[oc];
        float scale = gamma * (float)(1.0 / sqrt(var + 1e-5));
        float shift = beta - (float)mean * scale;
        g_bnp[e][oc] = make_float2(scale, shift);
    }
}

// ---------------- kernel 8: routed main conv via mma.sync (fp16 -> fp32) ----------------
// Block = 4 output rows x 128 oc. 512 thr = 16 warps; warp = 32 oc x 56 px (one row).
// Per (ic-chunk=16, tap): [128x16] @ [16x224] mma GEMM; B tap-shift via smem offset.
template<int K>
__device__ void conv_mma(const __half* __restrict__ Wh, int b, int r0,
                         float acc[2][7][4], __half* Bs0, __half* Bs1,
                         __half* As0, __half* As1, int warp, int lane) {
    const int PAD = K / 2;
    const int RIN = 4 + K - 1;         // 6 or 8
    const int CIN = 56 + K - 1;        // 58 or 60
    const int K2 = K * K;
    int tid = threadIdx.x;
    const __half* xb = g_xh + (size_t)b * NHW * NC;

    auto stageB = [&](int chunk, __half* Bb) {
        int ic0 = chunk * 16;
        int tot = RIN * CIN * 2;
        for (int idx = tid; idx < tot; idx += 512) {
            int hsel = idx & 1, i2 = idx >> 1;
            int i = i2 / CIN, j = i2 % CIN;
            int xr = r0 + i - PAD, xc = j - PAD;
            bool ok = (xr >= 0 && xr < NH && xc >= 0 && xc < NWW);
            int xrc = xr < 0 ? 0 : (xr > 55 ? 55 : xr);
            int xcc = xc < 0 ? 0 : (xc > 55 ? 55 : xc);
            const __half* src = xb + ((size_t)(xrc * 56 + xcc)) * NC + ic0 + hsel * 8;
            cpa16(s2u(Bb + (i * CIN + j) * 16 + hsel * 8), src, ok);
        }
    };
    auto stageA = [&](int chunk, int t, __half* Ab) {
        int ic0 = chunk * 16;
        if (tid < 256) {
            int oc = tid >> 1, h = tid & 1;
            cpa16(s2u(Ab + oc * 16 + h * 8),
                  Wh + ((size_t)t * NC + oc) * NC + ic0 + h * 8, true);
        }
    };

    int gid = lane >> 2, tig = lane & 3;
    int oc0 = (warp >> 2) * 32, rr = warp & 3;

    stageB(0, Bs0); stageA(0, 0, As0); cpa_commit();
    int apar = 0, bpar = 0;
    for (int c = 0; c < 8; c++) {
        for (int t = 0; t < K2; t++) {
            int nap = apar ^ 1;
            if (t + 1 < K2) stageA(c, t + 1, nap ? As1 : As0);
            else if (c + 1 < 8) {
                stageB(c + 1, (bpar ^ 1) ? Bs1 : Bs0);
                stageA(c + 1, 0, nap ? As1 : As0);
            }
            cpa_commit();
            cpa_wait<1>();
            __syncthreads();
            const __half* As = apar ? As1 : As0;
            const __half* Bs = bpar ? Bs1 : Bs0;
            int dy = t / K, dx = t % K;
            unsigned a[2][4];
#pragma unroll
            for (int mf = 0; mf < 2; mf++) {
                int r = oc0 + mf * 16 + gid;
                a[mf][0] = *(const unsigned*)(As + r * 16 + tig * 2);
                a[mf][1] = *(const unsigned*)(As + (r + 8) * 16 + tig * 2);
                a[mf][2] = *(const unsigned*)(As + r * 16 + tig * 2 + 8);
                a[mf][3] = *(const unsigned*)(As + (r + 8) * 16 + tig * 2 + 8);
            }
            int rowi = rr + dy;
#pragma unroll
            for (int nf = 0; nf < 7; nf++) {
                const __half* bp = Bs + ((rowi * CIN) + nf * 8 + gid + dx) * 16 + tig * 2;
                unsigned b0 = *(const unsigned*)bp;
                unsigned b1 = *(const unsigned*)(bp + 8);
                mma16816(acc[0][nf], a[0], b0, b1);
                mma16816(acc[1][nf], a[1], b0, b1);
            }
            __syncthreads();
            apar = nap;
        }
        bpar ^= 1;
    }
}

__global__ __launch_bounds__(512, 1) void k_out_mma(float* __restrict__ out) {
    __shared__ __align__(16) __half Bs[2][8 * 60 * 16];
    __shared__ __align__(16) __half As[2][NC * 16];
    int rt = blockIdx.x, b = blockIdx.y;
    int r0 = rt * 4;
    int e = g_top1[b];
    int warp = threadIdx.x >> 5, lane = threadIdx.x & 31;
    float acc[2][7][4];
#pragma unroll
    for (int mf = 0; mf < 2; mf++)
#pragma unroll
        for (int nf = 0; nf < 7; nf++)
#pragma unroll
            for (int k = 0; k < 4; k++) acc[mf][nf][k] = 0.f;

    if (e == 1)
        conv_mma<5>(g_wh5, b, r0, acc, Bs[0], Bs[1], As[0], As[1], warp, lane);
    else
        conv_mma<3>(e == 0 ? g_wh3cd : g_wh3sh, b, r0, acc, Bs[0], Bs[1], As[0], As[1], warp, lane);

    int gid = lane >> 2, tig = lane & 3;
    int oc0 = (warp >> 2) * 32, rr = warp & 3;
    int row = r0 + rr;
    const float* tbase = (e == 2) ? g_t_srm : g_t_hf;
#pragma unroll
    for (int mf = 0; mf < 2; mf++)
#pragma unroll
        for (int nf = 0; nf < 7; nf++)
#pragma unroll
            for (int h = 0; h < 2; h++) {
                int oc = oc0 + mf * 16 + gid + h * 8;
                int c = nf * 8 + tig * 2;
                float v0 = acc[mf][nf][h * 2 + 0], v1 = acc[mf][nf][h * 2 + 1];
                size_t off = (size_t)(b * NC + oc) * NHW + row * 56 + c;
                if (e >= 2) {
                    float2 bnp2 = g_bnp[e - 2][oc];
                    float2 tv = *(const float2*)(tbase + off);
                    v0 += fmaxf(tv.x * bnp2.x + bnp2.y, 0.f);
                    v1 += fmaxf(tv.y * bnp2.x + bnp2.y, 0.f);
                }
                float2 vv; vv.x = v0; vv.y = v1;
                *(float2*)(out + off) = vv;
            }
}

// ---------------- launcher ----------------
extern "C" void kernel_launch(void* const* d_in, const int* in_sizes, int n_in,
                              void* d_out, int out_size) {
    const float* x      = (const float*)d_in[0];
    const float* Wg     = (const float*)d_in[1];
    const float* cd_w   = (const float*)d_in[2];
    const float* bayar  = (const float*)d_in[3];
    const float* srm_k  = (const float*)d_in[4];
    const float* srm_ow = (const float*)d_in[5];
    const float* srm_g  = (const float*)d_in[6];
    const float* srm_b  = (const float*)d_in[7];
    const float* hf_k   = (const float*)d_in[8];
    const float* hf_ow  = (const float*)d_in[9];
    const float* hf_g   = (const float*)d_in[10];
    const float* hf_b   = (const float*)d_in[11];
    const float* shw    = (const float*)d_in[12];
    float* out = (float*)d_out;

    k_prep<<<(NC * NC + 127) / 128, 128>>>(cd_w, bayar, shw);
    k_xh<<<dim3(56, NB), 256>>>(x);
    k_pool<<<NB * NC, 128>>>(x);
    k_gate<<<1, 32>>>(Wg, out);
    k_dw_srm<<<NB * NC, 256>>>(x, srm_k);
    k_dw_hf<<<NB * NC, 256>>>(x, hf_k);
    k_c1x1<<<dim3(28, NB), 448>>>(srm_ow, 384, 2);
    k_c1x1<<<dim3(28, NB), 448>>>(hf_ow, 128, 3);
    k_bn<<<256, 64>>>(srm_g, srm_b, hf_g, hf_b);
    k_out_mma<<<dim3(14, NB), 512>>>(out);
}

// round 9
// speedup vs baseline: 4.1426x; 1.4846x over previous
#include <cuda_runtime.h>
#include <cuda_bf16.h>
#include <cuda_fp16.h>
#include <math.h>

constexpr int NB  = 32;
constexpr int NC  = 128;
constexpr int NH  = 56, NWW = 56;
constexpr int NHW = NH * NWW;                 // 3136
constexpr int NCHW = NC * NHW;                // 401408
constexpr long long TAILOFF = (long long)NB * NCHW;   // 12845056
constexpr float THETA = 0.7f;

// ---------------- scratch ----------------
__device__ float  g_pooled[NB * NC];
__device__ int    g_top1[NB];
__device__ __align__(16) __half g_xh[(size_t)NB * NHW * NC];
__device__ __align__(16) __half g_wh3cd[9 * NC * NC];
__device__ __align__(16) __half g_wh3sh[9 * NC * NC];
__device__ __align__(16) __half g_wh5[25 * NC * NC];
__device__ __align__(16) __half g_w1srm[NC * 384];
__device__ __align__(16) __half g_w1hf[NC * NC];
__device__ __align__(16) __half g_y_srm[(size_t)NB * 384 * NHW];     // planar
__device__ __align__(16) __half g_yb_srm[(size_t)NB * 384 * NHW];    // blocked [b][c16][px][16]
__device__ __align__(16) __half g_y_hf [(size_t)NB * NCHW];
__device__ __align__(16) __half g_yb_hf[(size_t)NB * NCHW];
__device__ float  g_t_srm[(size_t)NB * NCHW];
__device__ float  g_t_hf [(size_t)NB * NCHW];
__device__ float  g_psum[2][NC * 448];
__device__ float  g_psq [2][NC * 448];
__device__ float2 g_bnp[2][NC];

// ---------------- f32x2 helpers ----------------
typedef unsigned long long F2;
__device__ __forceinline__ F2 f2pack(float lo, float hi) {
    F2 r; asm("mov.b64 %0, {%1,%2};" : "=l"(r) : "f"(lo), "f"(hi)); return r;
}
__device__ __forceinline__ F2 f2dup(float v) { return f2pack(v, v); }
__device__ __forceinline__ void f2fma(F2 &acc, F2 a, F2 b) {
    asm("fma.rn.f32x2 %0, %1, %2, %0;" : "+l"(acc) : "l"(a), "l"(b));
}
__device__ __forceinline__ void f2unpack(F2 v, float &lo, float &hi) {
    asm("mov.b64 {%0,%1}, %2;" : "=f"(lo), "=f"(hi) : "l"(v));
}

// ---------------- cp.async helpers ----------------
__device__ __forceinline__ unsigned s2u(const void* p) {
    return (unsigned)__cvta_generic_to_shared(p);
}
__device__ __forceinline__ void cpa16(unsigned dst, const void* src, bool pred) {
    asm volatile("cp.async.cg.shared.global [%0], [%1], 16, %2;"
                 :: "r"(dst), "l"(src), "r"(pred ? 16 : 0));
}
__device__ __forceinline__ void cpa_commit() { asm volatile("cp.async.commit_group;"); }
template<int N>
__device__ __forceinline__ void cpa_wait() { asm volatile("cp.async.wait_group %0;" :: "n"(N)); }

// ---------------- mma m16n8k16 fp16->fp32 ----------------
__device__ __forceinline__ void mma16816(float c[4], const unsigned a[4], unsigned b0, unsigned b1) {
    asm volatile("mma.sync.aligned.m16n8k16.row.col.f32.f16.f16.f32 "
                 "{%0,%1,%2,%3}, {%4,%5,%6,%7}, {%8,%9}, {%0,%1,%2,%3};"
                 : "+f"(c[0]), "+f"(c[1]), "+f"(c[2]), "+f"(c[3])
                 : "r"(a[0]), "r"(a[1]), "r"(a[2]), "r"(a[3]), "r"(b0), "r"(b1));
}

// ---------------- kernel 1: fold expert kernels -> fp16 [tap][oc][ic] ----------------
__global__ void k_prep(const float* __restrict__ cd, const float* __restrict__ bayar,
                       const float* __restrict__ shw) {
    int t = blockIdx.x * blockDim.x + threadIdx.x;
    if (t >= NC * NC) return;
    const float* cw = cd  + (long long)t * 9;
    const float* sw = shw + (long long)t * 9;
    float s = 0.f;
#pragma unroll
    for (int k = 0; k < 9; k++) s += cw[k];
#pragma unroll
    for (int k = 0; k < 9; k++) {
        float v = cw[k] + sw[k] - (k == 4 ? THETA * s : 0.f);
        g_wh3cd[k * (NC * NC) + t] = __float2half(v);
        g_wh3sh[k * (NC * NC) + t] = __float2half(sw[k]);
    }
    const float* br = bayar + (long long)t * 24;
    float bs = 0.f;
#pragma unroll
    for (int k = 0; k < 24; k++) bs += br[k];
    float inv = 1.f / bs;
#pragma unroll
    for (int k = 0; k < 25; k++) {
        float v;
        if (k < 12) v = br[k] * inv;
        else if (k == 12) v = -1.f;
        else v = br[k - 1] * inv;
        int r = k / 5, c = k % 5;
        if (r >= 1 && r <= 3 && c >= 1 && c <= 3) v += sw[(r - 1) * 3 + (c - 1)];
        g_wh5[k * (NC * NC) + t] = __float2half(v);
    }
}

// ---------------- kernel 1b: 1x1 weights -> fp16 ----------------
__global__ void k_prepw(const float* __restrict__ srm_ow, const float* __restrict__ hf_ow) {
    int i = blockIdx.x * 256 + threadIdx.x;
    if (i < NC * 384) g_w1srm[i] = __float2half(srm_ow[i]);
    if (i < NC * NC)  g_w1hf[i]  = __float2half(hf_ow[i]);
}

// ---------------- kernel 1c: x -> channels-last fp16 ----------------
__global__ void k_xh(const float* __restrict__ x) {
    __shared__ float sm[128][57];
    int row = blockIdx.x, b = blockIdx.y;
    const float* xp = x + (size_t)b * NCHW + row * 56;
    for (int idx = threadIdx.x; idx < 128 * 56; idx += 256) {
        int ic = idx / 56, c = idx % 56;
        sm[ic][c] = xp[(size_t)ic * NHW + c];
    }
    __syncthreads();
    __half2* outp = (__half2*)(g_xh + ((size_t)b * NHW + row * 56) * NC);
    for (int idx = threadIdx.x; idx < 56 * 64; idx += 256) {
        int c = idx / 64, icp = idx % 64;
        outp[c * 64 + icp] = __floats2half2_rn(sm[icp * 2][c], sm[icp * 2 + 1][c]);
    }
}

// ---------------- kernel 2: spatial mean pool ----------------
__global__ void k_pool(const float* __restrict__ x) {
    int bc = blockIdx.x;
    const float* p = x + (long long)bc * NHW;
    float s = 0.f;
    for (int i = threadIdx.x; i < NHW; i += 128) s += p[i];
    __shared__ float sm[4];
#pragma unroll
    for (int o = 16; o > 0; o >>= 1) s += __shfl_down_sync(0xffffffff, s, o);
    if ((threadIdx.x & 31) == 0) sm[threadIdx.x >> 5] = s;
    __syncthreads();
    if (threadIdx.x == 0) g_pooled[bc] = (sm[0] + sm[1] + sm[2] + sm[3]) * (1.f / NHW);
}

// ---------------- kernel 3: gating + aux outputs ----------------
__global__ void k_gate(const float* __restrict__ Wg, float* __restrict__ out) {
    int b = threadIdx.x;
    if (b < NB) {
        float a0 = 0, a1 = 0, a2 = 0, a3 = 0;
        for (int c = 0; c < NC; c++) {
            float p = g_pooled[b * NC + c];
            a0 += p * Wg[c * 4 + 0]; a1 += p * Wg[c * 4 + 1];
            a2 += p * Wg[c * 4 + 2]; a3 += p * Wg[c * 4 + 3];
        }
        float l[4] = {a0, a1, a2, a3};
        int best = 0;
        for (int e = 1; e < 4; e++) if (l[e] > l[best]) best = e;
        g_top1[b] = best;
        for (int e = 0; e < 4; e++) out[TAILOFF + 9 + b * 4 + e] = (e == best) ? 1.f : 0.f;
    }
    __syncwarp();
    if (threadIdx.x == 0) {
        float cnt[4] = {0, 0, 0, 0};
        for (int bb = 0; bb < NB; bb++) cnt[g_top1[bb]] += 1.f;
        float mean = (cnt[0] + cnt[1] + cnt[2] + cnt[3]) * 0.25f;
        float var = 0.f;
        for (int e = 0; e < 4; e++) { float d = cnt[e] - mean; var += d * d; }
        var *= 0.25f;
        out[TAILOFF] = var / (mean * mean + 1e-10f);
        for (int e = 0; e < 4; e++) { out[TAILOFF + 1 + e] = cnt[e]; out[TAILOFF + 5 + e] = cnt[e]; }
    }
}

// ---------------- kernel 4: SRM depthwise 5x5 + hardtanh -> fp16, f32x2 8px/unit --------
__global__ __launch_bounds__(256, 2) void k_dw_srm(const float* __restrict__ x,
                                                   const float* __restrict__ kern) {
    __shared__ __align__(16) float xt[60 * 60];
    __shared__ float kf[75];
    int b = blockIdx.x >> 7, ch = blockIdx.x & 127;
    const float* xs = x + (size_t)(b * NC + ch) * NHW;
    for (int idx = threadIdx.x; idx < 3600; idx += 256) {
        int r = idx / 60, c = idx % 60, gr = r - 2, gc = c - 2;
        xt[idx] = (gr >= 0 && gr < 56 && gc >= 0 && gc < 56) ? xs[gr * 56 + gc] : 0.f;
    }
    if (threadIdx.x < 75) kf[threadIdx.x] = kern[ch * 75 + threadIdx.x];
    __syncthreads();
    __half* yo = g_y_srm + (size_t)(b * 384 + 3 * ch) * NHW;
    for (int u = threadIdx.x; u < 392; u += 256) {
        int r = u / 7, c0 = (u % 7) * 8;
        F2 acc[3][4];
#pragma unroll
        for (int f = 0; f < 3; f++)
#pragma unroll
            for (int q = 0; q < 4; q++) acc[f][q] = 0ULL;
#pragma unroll
        for (int dy = 0; dy < 5; dy++) {
            float xr[12];
            const float2* xp = (const float2*)(xt + (r + dy) * 60 + c0);
#pragma unroll
            for (int q = 0; q < 6; q++) { float2 v = xp[q]; xr[2 * q] = v.x; xr[2 * q + 1] = v.y; }
#pragma unroll
            for (int dx = 0; dx < 5; dx++) {
                F2 xv[4];
#pragma unroll
                for (int q = 0; q < 4; q++) xv[q] = f2pack(xr[dx + 2 * q], xr[dx + 2 * q + 1]);
#pragma unroll
                for (int f = 0; f < 3; f++) {
                    F2 wv = f2dup(kf[f * 25 + dy * 5 + dx]);
#pragma unroll
                    for (int q = 0; q < 4; q++) f2fma(acc[f][q], xv[q], wv);
                }
            }
        }
#pragma unroll
        for (int f = 0; f < 3; f++) {
            __half2 h[4];
#pragma unroll
            for (int q = 0; q < 4; q++) {
                float lo, hi; f2unpack(acc[f][q], lo, hi);
                lo = fminf(fmaxf(lo, -3.f), 3.f);
                hi = fminf(fmaxf(hi, -3.f), 3.f);
                h[q] = __floats2half2_rn(lo, hi);
            }
            *(uint4*)(yo + (size_t)f * NHW + r * 56 + c0) = *(uint4*)h;
        }
    }
}

// ---------------- kernel 5: HF depthwise 3x3 -> fp16, f32x2 8px/unit ----------------
__global__ __launch_bounds__(256, 2) void k_dw_hf(const float* __restrict__ x,
                                                  const float* __restrict__ kern) {
    __shared__ __align__(16) float xt[58 * 58];
    __shared__ float kfs[9];
    int b = blockIdx.x >> 7, ch = blockIdx.x & 127;
    const float* xs = x + (size_t)(b * NC + ch) * NHW;
    for (int idx = threadIdx.x; idx < 58 * 58; idx += 256) {
        int r = idx / 58, c = idx % 58, gr = r - 1, gc = c - 1;
        xt[idx] = (gr >= 0 && gr < 56 && gc >= 0 && gc < 56) ? xs[gr * 56 + gc] : 0.f;
    }
    if (threadIdx.x < 9) kfs[threadIdx.x] = kern[ch * 9 + threadIdx.x];
    __syncthreads();
    float kr[9];
#pragma unroll
    for (int k = 0; k < 9; k++) kr[k] = kfs[k];
    __half* yo = g_y_hf + (size_t)(b * NC + ch) * NHW;
    for (int u = threadIdx.x; u < 392; u += 256) {
        int r = u / 7, c0 = (u % 7) * 8;
        F2 acc[4];
#pragma unroll
        for (int q = 0; q < 4; q++) acc[q] = 0ULL;
#pragma unroll
        for (int dy = 0; dy < 3; dy++) {
            float xr[10];
            const float2* xp = (const float2*)(xt + (r + dy) * 58 + c0);
#pragma unroll
            for (int q = 0; q < 5; q++) { float2 v = xp[q]; xr[2 * q] = v.x; xr[2 * q + 1] = v.y; }
#pragma unroll
            for (int dx = 0; dx < 3; dx++) {
                F2 wv = f2dup(kr[dy * 3 + dx]);
#pragma unroll
                for (int q = 0; q < 4; q++) f2fma(acc[q], f2pack(xr[dx + 2 * q], xr[dx + 2 * q + 1]), wv);
            }
        }
        __half2 h[4];
#pragma unroll
        for (int q = 0; q < 4; q++) {
            float lo, hi; f2unpack(acc[q], lo, hi);
            h[q] = __floats2half2_rn(lo, hi);
        }
        *(uint4*)(yo + r * 56 + c0) = *(uint4*)h;
    }
}

// ---------------- kernel 5b: transpose y planar -> blocked [b][chunk][px][16] ----------
__global__ __launch_bounds__(256) void k_ytr(int which) {   // 0 = srm (24 chunks), 1 = hf (8)
    __shared__ __align__(16) __half sm[16][400];
    int chunks = which ? 8 : 24;
    const __half* src = which ? g_y_hf : g_y_srm;
    __half* dst = which ? g_yb_hf : g_yb_srm;
    int pt = blockIdx.x, c = blockIdx.y, b = blockIdx.z;
    const __half* s = src + ((size_t)(b * chunks + c) * 16) * NHW + pt * 392;
    for (int i = threadIdx.x; i < 784; i += 256) {
        int ic = i / 49, k = i % 49;
        cpa16(s2u(&sm[ic][k * 8]), s + (size_t)ic * NHW + k * 8, true);
    }
    cpa_commit(); cpa_wait<0>();
    __syncthreads();
    __half* d = dst + ((size_t)(b * chunks + c) * NHW + pt * 392) * 16;
    for (int p = threadIdx.x; p < 392; p += 256) {
        __half tmp[16];
#pragma unroll
        for (int ic = 0; ic < 16; ic++) tmp[ic] = sm[ic][p];
        *(uint4*)(d + (size_t)p * 16) = *(uint4*)tmp;
        *(uint4*)(d + (size_t)p * 16 + 8) = *(uint4*)(tmp + 8);
    }
}

// ---------------- kernel 6: 1x1 conv via mma + BN partials ----------------
// Block = (b, pt of 224 px). 512 thr, 16 warps; warp = 32 oc x 56 px.
__global__ __launch_bounds__(512, 1) void k_c1x1_mma(int chunks, int eid) {
    __shared__ __align__(16) __half As[2][NC * 16];
    __shared__ __align__(16) __half Bs[2][224 * 16];
    __shared__ float red[NC][8];
    const __half* yb_all = (eid == 2) ? g_yb_srm : g_yb_hf;
    const __half* Wh     = (eid == 2) ? g_w1srm  : g_w1hf;
    float* tout          = (eid == 2) ? g_t_srm  : g_t_hf;
    float* psum = g_psum[eid - 2];
    float* psq  = g_psq [eid - 2];

    int pt = blockIdx.x, b = blockIdx.y;
    int px0 = pt * 224;
    int tid = threadIdx.x, warp = tid >> 5, lane = tid & 31;
    int wm = warp >> 2, wn = warp & 3;
    int gid = lane >> 2, tig = lane & 3;
    int Cin = chunks * 16;
    const __half* yb = yb_all + (size_t)b * chunks * NHW * 16;

    float acc[2][7][4];
#pragma unroll
    for (int mf = 0; mf < 2; mf++)
#pragma unroll
        for (int nf = 0; nf < 7; nf++)
#pragma unroll
            for (int k = 0; k < 4; k++) acc[mf][nf][k] = 0.f;

    auto stage = [&](int c, int buf) {
#pragma unroll
        for (int k = 0; k < 2; k++) {
            int idx = tid + k * 512;
            if (idx < 448) {
                int p = idx >> 1, h = idx & 1;
                cpa16(s2u(Bs[buf] + p * 16 + h * 8),
                      yb + ((size_t)c * NHW + px0 + p) * 16 + h * 8, true);
            } else if (idx < 704) {
                int i2 = idx - 448;
                int oc = i2 >> 1, h = i2 & 1;
                cpa16(s2u(As[buf] + oc * 16 + h * 8),
                      Wh + (size_t)oc * Cin + c * 16 + h * 8, true);
            }
        }
    };

    stage(0, 0); cpa_commit();
    int buf = 0;
    for (int c = 0; c < chunks; c++) {
        if (c + 1 < chunks) { stage(c + 1, buf ^ 1); cpa_commit(); cpa_wait<1>(); }
        else cpa_wait<0>();
        __syncthreads();
        const __half* Asb = As[buf];
        const __half* Bsb = Bs[buf];
        unsigned a[2][4];
#pragma unroll
        for (int mf = 0; mf < 2; mf++) {
            int r = wm * 32 + mf * 16 + gid;
            a[mf][0] = *(const unsigned*)(Asb + r * 16 + tig * 2);
            a[mf][1] = *(const unsigned*)(Asb + (r + 8) * 16 + tig * 2);
            a[mf][2] = *(const unsigned*)(Asb + r * 16 + tig * 2 + 8);
            a[mf][3] = *(const unsigned*)(Asb + (r + 8) * 16 + tig * 2 + 8);
        }
#pragma unroll
        for (int nf = 0; nf < 7; nf++) {
            const __half* bp = Bsb + (wn * 56 + nf * 8 + gid) * 16 + tig * 2;
            unsigned b0 = *(const unsigned*)bp;
            unsigned b1 = *(const unsigned*)(bp + 8);
            mma16816(acc[0][nf], a[0], b0, b1);
            mma16816(acc[1][nf], a[1], b0, b1);
        }
        __syncthreads();
        buf ^= 1;
    }

    bool sel = (g_top1[b] == eid);
#pragma unroll
    for (int mf = 0; mf < 2; mf++)
#pragma unroll
        for (int h = 0; h < 2; h++) {
            int oc = wm * 32 + mf * 16 + gid + h * 8;
            float s = 0.f, q = 0.f;
#pragma unroll
            for (int nf = 0; nf < 7; nf++) {
                float v0 = acc[mf][nf][h * 2 + 0], v1 = acc[mf][nf][h * 2 + 1];
                s += v0 + v1; q += v0 * v0 + v1 * v1;
                if (sel) {
                    int px = px0 + wn * 56 + nf * 8 + tig * 2;
                    float2 vv; vv.x = v0; vv.y = v1;
                    *(float2*)(tout + (size_t)(b * NC + oc) * NHW + px) = vv;
                }
            }
            s += __shfl_xor_sync(0xffffffffu, s, 1);
            s += __shfl_xor_sync(0xffffffffu, s, 2);
            q += __shfl_xor_sync(0xffffffffu, q, 1);
            q += __shfl_xor_sync(0xffffffffu, q, 2);
            if (tig == 0) { red[oc][wn] = s; red[oc][4 + wn] = q; }
        }
    __syncthreads();
    if (tid < NC) {
        float ss = red[tid][0] + red[tid][1] + red[tid][2] + red[tid][3];
        float qq = red[tid][4] + red[tid][5] + red[tid][6] + red[tid][7];
        psum[tid * 448 + b * 14 + pt] = ss;
        psq [tid * 448 + b * 14 + pt] = qq;
    }
}

// ---------------- kernel 7: finish BN stats ----------------
__global__ void k_bn(const float* __restrict__ srm_g, const float* __restrict__ srm_b,
                     const float* __restrict__ hf_g,  const float* __restrict__ hf_b) {
    int e = blockIdx.x >> 7, oc = blockIdx.x & 127;
    __shared__ double sm0[64], sm1[64];
    double s = 0.0, q = 0.0;
    for (int i = threadIdx.x; i < 448; i += 64) {
        s += (double)g_psum[e][oc * 448 + i];
        q += (double)g_psq [e][oc * 448 + i];
    }
    sm0[threadIdx.x] = s; sm1[threadIdx.x] = q;
    __syncthreads();
    for (int o = 32; o > 0; o >>= 1) {
        if (threadIdx.x < o) { sm0[threadIdx.x] += sm0[threadIdx.x + o]; sm1[threadIdx.x] += sm1[threadIdx.x + o]; }
        __syncthreads();
    }
    if (threadIdx.x == 0) {
        double N = (double)NB * NHW;
        double mean = sm0[0] / N;
        double var  = sm1[0] / N - mean * mean;
        if (var < 0.0) var = 0.0;
        float gamma = e ? hf_g[oc] : srm_g[oc];
        float beta  = e ? hf_b[oc] : srm_b[oc];
        float scale = gamma * (float)(1.0 / sqrt(var + 1e-5));
        float shift = beta - (float)mean * scale;
        g_bnp[e][oc] = make_float2(scale, shift);
    }
}

// ---------------- kernel 8: routed main conv via mma.sync ----------------
template<int K>
__device__ void conv_mma(const __half* __restrict__ Wh, int b, int r0,
                         float acc[2][7][4], __half* Bs0, __half* Bs1,
                         __half* As0, __half* As1, int warp, int lane) {
    const int PAD = K / 2;
    const int RIN = 4 + K - 1;
    const int CIN = 56 + K - 1;
    const int K2 = K * K;
    int tid = threadIdx.x;
    const __half* xb = g_xh + (size_t)b * NHW * NC;

    auto stageB = [&](int chunk, __half* Bb) {
        int ic0 = chunk * 16;
        int tot = RIN * CIN * 2;
        for (int idx = tid; idx < tot; idx += 512) {
            int hsel = idx & 1, i2 = idx >> 1;
            int i = i2 / CIN, j = i2 % CIN;
            int xr = r0 + i - PAD, xc = j - PAD;
            bool ok = (xr >= 0 && xr < NH && xc >= 0 && xc < NWW);
            int xrc = xr < 0 ? 0 : (xr > 55 ? 55 : xr);
            int xcc = xc < 0 ? 0 : (xc > 55 ? 55 : xc);
            const __half* src = xb + ((size_t)(xrc * 56 + xcc)) * NC + ic0 + hsel * 8;
            cpa16(s2u(Bb + (i * CIN + j) * 16 + hsel * 8), src, ok);
        }
    };
    auto stageA = [&](int chunk, int t, __half* Ab) {
        int ic0 = chunk * 16;
        if (tid < 256) {
            int oc = tid >> 1, h = tid & 1;
            cpa16(s2u(Ab + oc * 16 + h * 8),
                  Wh + ((size_t)t * NC + oc) * NC + ic0 + h * 8, true);
        }
    };

    int gid = lane >> 2, tig = lane & 3;
    int oc0 = (warp >> 2) * 32, rr = warp & 3;

    stageB(0, Bs0); stageA(0, 0, As0); cpa_commit();
    int apar = 0, bpar = 0;
    for (int c = 0; c < 8; c++) {
        for (int t = 0; t < K2; t++) {
            int nap = apar ^ 1;
            if (t + 1 < K2) stageA(c, t + 1, nap ? As1 : As0);
            else if (c + 1 < 8) {
                stageB(c + 1, (bpar ^ 1) ? Bs1 : Bs0);
                stageA(c + 1, 0, nap ? As1 : As0);
            }
            cpa_commit();
            cpa_wait<1>();
            __syncthreads();
            const __half* As = apar ? As1 : As0;
            const __half* Bs = bpar ? Bs1 : Bs0;
            int dy = t / K, dx = t % K;
            unsigned a[2][4];
#pragma unroll
            for (int mf = 0; mf < 2; mf++) {
                int r = oc0 + mf * 16 + gid;
                a[mf][0] = *(const unsigned*)(As + r * 16 + tig * 2);
                a[mf][1] = *(const unsigned*)(As + (r + 8) * 16 + tig * 2);
                a[mf][2] = *(const unsigned*)(As + r * 16 + tig * 2 + 8);
                a[mf][3] = *(const unsigned*)(As + (r + 8) * 16 + tig * 2 + 8);
            }
            int rowi = rr + dy;
#pragma unroll
            for (int nf = 0; nf < 7; nf++) {
                const __half* bp = Bs + ((rowi * CIN) + nf * 8 + gid + dx) * 16 + tig * 2;
                unsigned b0 = *(const unsigned*)bp;
                unsigned b1 = *(const unsigned*)(bp + 8);
                mma16816(acc[0][nf], a[0], b0, b1);
                mma16816(acc[1][nf], a[1], b0, b1);
            }
            __syncthreads();
            apar = nap;
        }
        bpar ^= 1;
    }
}

__global__ __launch_bounds__(512, 1) void k_out_mma(float* __restrict__ out) {
    __shared__ __align__(16) __half Bs[2][8 * 60 * 16];
    __shared__ __align__(16) __half As[2][NC * 16];
    int rt = blockIdx.x, b = blockIdx.y;
    int r0 = rt * 4;
    int e = g_top1[b];
    int warp = threadIdx.x >> 5, lane = threadIdx.x & 31;
    float acc[2][7][4];
#pragma unroll
    for (int mf = 0; mf < 2; mf++)
#pragma unroll
        for (int nf = 0; nf < 7; nf++)
#pragma unroll
            for (int k = 0; k < 4; k++) acc[mf][nf][k] = 0.f;

    if (e == 1)
        conv_mma<5>(g_wh5, b, r0, acc, Bs[0], Bs[1], As[0], As[1], warp, lane);
    else
        conv_mma<3>(e == 0 ? g_wh3cd : g_wh3sh, b, r0, acc, Bs[0], Bs[1], As[0], As[1], warp, lane);

    int gid = lane >> 2, tig = lane & 3;
    int oc0 = (warp >> 2) * 32, rr = warp & 3;
    int row = r0 + rr;
    const float* tbase = (e == 2) ? g_t_srm : g_t_hf;
#pragma unroll
    for (int mf = 0; mf < 2; mf++)
#pragma unroll
        for (int nf = 0; nf < 7; nf++)
#pragma unroll
            for (int h = 0; h < 2; h++) {
                int oc = oc0 + mf * 16 + gid + h * 8;
                int c = nf * 8 + tig * 2;
                float v0 = acc[mf][nf][h * 2 + 0], v1 = acc[mf][nf][h * 2 + 1];
                size_t off = (size_t)(b * NC + oc) * NHW + row * 56 + c;
                if (e >= 2) {
                    float2 bnp2 = g_bnp[e - 2][oc];
                    float2 tv = *(const float2*)(tbase + off);
                    v0 += fmaxf(tv.x * bnp2.x + bnp2.y, 0.f);
                    v1 += fmaxf(tv.y * bnp2.x + bnp2.y, 0.f);
                }
                float2 vv; vv.x = v0; vv.y = v1;
                *(float2*)(out + off) = vv;
            }
}

// ---------------- launcher ----------------
extern "C" void kernel_launch(void* const* d_in, const int* in_sizes, int n_in,
                              void* d_out, int out_size) {
    const float* x      = (const float*)d_in[0];
    const float* Wg     = (const float*)d_in[1];
    const float* cd_w   = (const float*)d_in[2];
    const float* bayar  = (const float*)d_in[3];
    const float* srm_k  = (const float*)d_in[4];
    const float* srm_ow = (const float*)d_in[5];
    const float* srm_g  = (const float*)d_in[6];
    const float* srm_b  = (const float*)d_in[7];
    const float* hf_k   = (const float*)d_in[8];
    const float* hf_ow  = (const float*)d_in[9];
    const float* hf_g   = (const float*)d_in[10];
    const float* hf_b   = (const float*)d_in[11];
    const float* shw    = (const float*)d_in[12];
    float* out = (float*)d_out;

    k_prep<<<(NC * NC + 127) / 128, 128>>>(cd_w, bayar, shw);
    k_prepw<<<(NC * 384 + 255) / 256, 256>>>(srm_ow, hf_ow);
    k_xh<<<dim3(56, NB), 256>>>(x);
    k_pool<<<NB * NC, 128>>>(x);
    k_gate<<<1, 32>>>(Wg, out);
    k_dw_srm<<<NB * NC, 256>>>(x, srm_k);
    k_dw_hf<<<NB * NC, 256>>>(x, hf_k);
    k_ytr<<<dim3(8, 24, NB), 256>>>(0);
    k_ytr<<<dim3(8, 8, NB), 256>>>(1);
    k_c1x1_mma<<<dim3(14, NB), 512>>>(24, 2);
    k_c1x1_mma<<<dim3(14, NB), 512>>>(8, 3);
    k_bn<<<256, 64>>>(srm_g, srm_b, hf_g, hf_b);
    k_out_mma<<<dim3(14, NB), 512>>>(out);
}

// round 11
// speedup vs baseline: 4.9803x; 1.2022x over previous
#include <cuda_runtime.h>
#include <cuda_bf16.h>
#include <cuda_fp16.h>
#include <math.h>

constexpr int NB  = 32;
constexpr int NC  = 128;
constexpr int NH  = 56, NWW = 56;
constexpr int NHW = NH * NWW;                 // 3136
constexpr int NCHW = NC * NHW;                // 401408
constexpr long long TAILOFF = (long long)NB * NCHW;   // 12845056
constexpr float THETA = 0.7f;

// ---------------- scratch ----------------
__device__ float  g_pooled[NB * NC];
__device__ int    g_top1[NB];
__device__ __align__(16) __half g_xh[(size_t)NB * NHW * NC];
__device__ __align__(16) __half g_wh3cd[9 * NC * NC];
__device__ __align__(16) __half g_wh3sh[9 * NC * NC];
__device__ __align__(16) __half g_wh5[25 * NC * NC];
__device__ __align__(16) __half g_w1srm[NC * 384];
__device__ __align__(16) __half g_w1hf[NC * NC];
__device__ __align__(16) __half g_y_srm[(size_t)NB * 384 * NHW];     // planar
__device__ __align__(16) __half g_y_hf [(size_t)NB * NCHW];
__device__ float  g_t_srm[(size_t)NB * NCHW];
__device__ float  g_t_hf [(size_t)NB * NCHW];
__device__ float  g_psum[2][NC * 448];
__device__ float  g_psq [2][NC * 448];
__device__ float2 g_bnp[2][NC];

// ---------------- f32x2 helpers ----------------
typedef unsigned long long F2;
__device__ __forceinline__ F2 f2pack(float lo, float hi) {
    F2 r; asm("mov.b64 %0, {%1,%2};" : "=l"(r) : "f"(lo), "f"(hi)); return r;
}
__device__ __forceinline__ F2 f2dup(float v) { return f2pack(v, v); }
__device__ __forceinline__ void f2fma(F2 &acc, F2 a, F2 b) {
    asm("fma.rn.f32x2 %0, %1, %2, %0;" : "+l"(acc) : "l"(a), "l"(b));
}
__device__ __forceinline__ void f2unpack(F2 v, float &lo, float &hi) {
    asm("mov.b64 {%0,%1}, %2;" : "=f"(lo), "=f"(hi) : "l"(v));
}

// ---------------- cp.async helpers ----------------
__device__ __forceinline__ unsigned s2u(const void* p) {
    return (unsigned)__cvta_generic_to_shared(p);
}
__device__ __forceinline__ void cpa16(unsigned dst, const void* src, bool pred) {
    asm volatile("cp.async.cg.shared.global [%0], [%1], 16, %2;"
                 :: "r"(dst), "l"(src), "r"(pred ? 16 : 0));
}
__device__ __forceinline__ void cpa_commit() { asm volatile("cp.async.commit_group;"); }
template<int N>
__device__ __forceinline__ void cpa_wait() { asm volatile("cp.async.wait_group %0;" :: "n"(N)); }

// ---------------- mma m16n8k16 fp16->fp32 ----------------
__device__ __forceinline__ void mma16816(float c[4], const unsigned a[4], unsigned b0, unsigned b1) {
    asm volatile("mma.sync.aligned.m16n8k16.row.col.f32.f16.f16.f32 "
                 "{%0,%1,%2,%3}, {%4,%5,%6,%7}, {%8,%9}, {%0,%1,%2,%3};"
                 : "+f"(c[0]), "+f"(c[1]), "+f"(c[2]), "+f"(c[3])
                 : "r"(a[0]), "r"(a[1]), "r"(a[2]), "r"(a[3]), "r"(b0), "r"(b1));
}

// ---------------- kernel 1: fold expert kernels + 1x1 weights -> fp16 ----------------
__global__ void k_prep(const float* __restrict__ cd, const float* __restrict__ bayar,
                       const float* __restrict__ shw, const float* __restrict__ srm_ow,
                       const float* __restrict__ hf_ow) {
    int t = blockIdx.x * blockDim.x + threadIdx.x;
    if (t >= NC * NC) return;
    const float* cw = cd  + (long long)t * 9;
    const float* sw = shw + (long long)t * 9;
    float s = 0.f;
#pragma unroll
    for (int k = 0; k < 9; k++) s += cw[k];
#pragma unroll
    for (int k = 0; k < 9; k++) {
        float v = cw[k] + sw[k] - (k == 4 ? THETA * s : 0.f);
        g_wh3cd[k * (NC * NC) + t] = __float2half(v);
        g_wh3sh[k * (NC * NC) + t] = __float2half(sw[k]);
    }
    const float* br = bayar + (long long)t * 24;
    float bs = 0.f;
#pragma unroll
    for (int k = 0; k < 24; k++) bs += br[k];
    float inv = 1.f / bs;
#pragma unroll
    for (int k = 0; k < 25; k++) {
        float v;
        if (k < 12) v = br[k] * inv;
        else if (k == 12) v = -1.f;
        else v = br[k - 1] * inv;
        int r = k / 5, c = k % 5;
        if (r >= 1 && r <= 3 && c >= 1 && c <= 3) v += sw[(r - 1) * 3 + (c - 1)];
        g_wh5[k * (NC * NC) + t] = __float2half(v);
    }
    // 1x1 weights
    g_w1hf[t] = __float2half(hf_ow[t]);
    g_w1srm[t]               = __float2half(srm_ow[t]);
    g_w1srm[t + NC * NC]     = __float2half(srm_ow[t + NC * NC]);
    g_w1srm[t + 2 * NC * NC] = __float2half(srm_ow[t + 2 * NC * NC]);
}

// ---------------- kernel 1c: x -> channels-last fp16 ----------------
__global__ void k_xh(const float* __restrict__ x) {
    __shared__ float sm[128][57];
    int row = blockIdx.x, b = blockIdx.y;
    const float* xp = x + (size_t)b * NCHW + row * 56;
    for (int idx = threadIdx.x; idx < 128 * 56; idx += 256) {
        int ic = idx / 56, c = idx % 56;
        sm[ic][c] = xp[(size_t)ic * NHW + c];
    }
    __syncthreads();
    __half2* outp = (__half2*)(g_xh + ((size_t)b * NHW + row * 56) * NC);
    for (int idx = threadIdx.x; idx < 56 * 64; idx += 256) {
        int c = idx / 64, icp = idx % 64;
        outp[c * 64 + icp] = __floats2half2_rn(sm[icp * 2][c], sm[icp * 2 + 1][c]);
    }
}

// ---------------- kernel 2: spatial mean pool ----------------
__global__ void k_pool(const float* __restrict__ x) {
    int bc = blockIdx.x;
    const float* p = x + (long long)bc * NHW;
    float s = 0.f;
    for (int i = threadIdx.x; i < NHW; i += 128) s += p[i];
    __shared__ float sm[4];
#pragma unroll
    for (int o = 16; o > 0; o >>= 1) s += __shfl_down_sync(0xffffffff, s, o);
    if ((threadIdx.x & 31) == 0) sm[threadIdx.x >> 5] = s;
    __syncthreads();
    if (threadIdx.x == 0) g_pooled[bc] = (sm[0] + sm[1] + sm[2] + sm[3]) * (1.f / NHW);
}

// ---------------- kernel 3: gating + aux outputs (smem-staged) ----------------
__global__ void k_gate(const float* __restrict__ Wg, float* __restrict__ out) {
    __shared__ float sp[NB * NC];
    __shared__ float sw[NC * 4];
    int tid = threadIdx.x;
    for (int i = tid; i < NB * NC; i += 128) sp[i] = g_pooled[i];
    for (int i = tid; i < NC * 4; i += 128) sw[i] = Wg[i];
    __syncthreads();
    int b = tid;
    if (b < NB) {
        float a0 = 0, a1 = 0, a2 = 0, a3 = 0;
        for (int c = 0; c < NC; c++) {
            float p = sp[b * NC + c];
            a0 += p * sw[c * 4 + 0]; a1 += p * sw[c * 4 + 1];
            a2 += p * sw[c * 4 + 2]; a3 += p * sw[c * 4 + 3];
        }
        float l[4] = {a0, a1, a2, a3};
        int best = 0;
        for (int e = 1; e < 4; e++) if (l[e] > l[best]) best = e;
        g_top1[b] = best;
        for (int e = 0; e < 4; e++) out[TAILOFF + 9 + b * 4 + e] = (e == best) ? 1.f : 0.f;
    }
    __syncthreads();
    if (tid == 0) {
        float cnt[4] = {0, 0, 0, 0};
        for (int bb = 0; bb < NB; bb++) cnt[g_top1[bb]] += 1.f;
        float mean = (cnt[0] + cnt[1] + cnt[2] + cnt[3]) * 0.25f;
        float var = 0.f;
        for (int e = 0; e < 4; e++) { float d = cnt[e] - mean; var += d * d; }
        var *= 0.25f;
        out[TAILOFF] = var / (mean * mean + 1e-10f);
        for (int e = 0; e < 4; e++) { out[TAILOFF + 1 + e] = cnt[e]; out[TAILOFF + 5 + e] = cnt[e]; }
    }
}

// ---------------- kernel 4: SRM depthwise 5x5 + hardtanh -> fp16, f32x2 8px/unit --------
__global__ __launch_bounds__(256, 2) void k_dw_srm(const float* __restrict__ x,
                                                   const float* __restrict__ kern) {
    __shared__ __align__(16) float xt[60 * 60];
    __shared__ float kf[75];
    int b = blockIdx.x >> 7, ch = blockIdx.x & 127;
    const float* xs = x + (size_t)(b * NC + ch) * NHW;
    for (int idx = threadIdx.x; idx < 3600; idx += 256) {
        int r = idx / 60, c = idx % 60, gr = r - 2, gc = c - 2;
        xt[idx] = (gr >= 0 && gr < 56 && gc >= 0 && gc < 56) ? xs[gr * 56 + gc] : 0.f;
    }
    if (threadIdx.x < 75) kf[threadIdx.x] = kern[ch * 75 + threadIdx.x];
    __syncthreads();
    __half* yo = g_y_srm + (size_t)(b * 384 + 3 * ch) * NHW;
    for (int u = threadIdx.x; u < 392; u += 256) {
        int r = u / 7, c0 = (u % 7) * 8;
        F2 acc[3][4];
#pragma unroll
        for (int f = 0; f < 3; f++)
#pragma unroll
            for (int q = 0; q < 4; q++) acc[f][q] = 0ULL;
#pragma unroll
        for (int dy = 0; dy < 5; dy++) {
            float xr[12];
            const float2* xp = (const float2*)(xt + (r + dy) * 60 + c0);
#pragma unroll
            for (int q = 0; q < 6; q++) { float2 v = xp[q]; xr[2 * q] = v.x; xr[2 * q + 1] = v.y; }
#pragma unroll
            for (int dx = 0; dx < 5; dx++) {
                F2 xv[4];
#pragma unroll
                for (int q = 0; q < 4; q++) xv[q] = f2pack(xr[dx + 2 * q], xr[dx + 2 * q + 1]);
#pragma unroll
                for (int f = 0; f < 3; f++) {
                    F2 wv = f2dup(kf[f * 25 + dy * 5 + dx]);
#pragma unroll
                    for (int q = 0; q < 4; q++) f2fma(acc[f][q], xv[q], wv);
                }
            }
        }
#pragma unroll
        for (int f = 0; f < 3; f++) {
            __half2 h[4];
#pragma unroll
            for (int q = 0; q < 4; q++) {
                float lo, hi; f2unpack(acc[f][q], lo, hi);
                lo = fminf(fmaxf(lo, -3.f), 3.f);
                hi = fminf(fmaxf(hi, -3.f), 3.f);
                h[q] = __floats2half2_rn(lo, hi);
            }
            *(uint4*)(yo + (size_t)f * NHW + r * 56 + c0) = *(uint4*)h;
        }
    }
}

// ---------------- kernel 5: HF depthwise 3x3 -> fp16, f32x2 8px/unit ----------------
__global__ __launch_bounds__(256, 2) void k_dw_hf(const float* __restrict__ x,
                                                  const float* __restrict__ kern) {
    __shared__ __align__(16) float xt[58 * 58];
    __shared__ float kfs[9];
    int b = blockIdx.x >> 7, ch = blockIdx.x & 127;
    const float* xs = x + (size_t)(b * NC + ch) * NHW;
    for (int idx = threadIdx.x; idx < 58 * 58; idx += 256) {
        int r = idx / 58, c = idx % 58, gr = r - 1, gc = c - 1;
        xt[idx] = (gr >= 0 && gr < 56 && gc >= 0 && gc < 56) ? xs[gr * 56 + gc] : 0.f;
    }
    if (threadIdx.x < 9) kfs[threadIdx.x] = kern[ch * 9 + threadIdx.x];
    __syncthreads();
    float kr[9];
#pragma unroll
    for (int k = 0; k < 9; k++) kr[k] = kfs[k];
    __half* yo = g_y_hf + (size_t)(b * NC + ch) * NHW;
    for (int u = threadIdx.x; u < 392; u += 256) {
        int r = u / 7, c0 = (u % 7) * 8;
        F2 acc[4];
#pragma unroll
        for (int q = 0; q < 4; q++) acc[q] = 0ULL;
#pragma unroll
        for (int dy = 0; dy < 3; dy++) {
            float xr[10];
            const float2* xp = (const float2*)(xt + (r + dy) * 58 + c0);
#pragma unroll
            for (int q = 0; q < 5; q++) { float2 v = xp[q]; xr[2 * q] = v.x; xr[2 * q + 1] = v.y; }
#pragma unroll
            for (int dx = 0; dx < 3; dx++) {
                F2 wv = f2dup(kr[dy * 3 + dx]);
#pragma unroll
                for (int q = 0; q < 4; q++) f2fma(acc[q], f2pack(xr[dx + 2 * q], xr[dx + 2 * q + 1]), wv);
            }
        }
        __half2 h[4];
#pragma unroll
        for (int q = 0; q < 4; q++) {
            float lo, hi; f2unpack(acc[q], lo, hi);
            h[q] = __floats2half2_rn(lo, hi);
        }
        *(uint4*)(yo + r * 56 + c0) = *(uint4*)h;
    }
}

// ---------------- kernel 6: 1x1 conv via mma from PLANAR y + BN partials ----------------
// Block = (pt of 224 px, b). 512 thr, 16 warps; warp = 32 oc x 56 px.
// B staged planar [16ic][232px-pad]; fragments built from 4x u16 LDS + packs.
__global__ __launch_bounds__(512, 1) void k_c1x1_mma(int chunks, int eid) {
    __shared__ __align__(16) __half As[2][NC * 16];
    __shared__ __align__(16) __half Bs[2][16 * 232];
    __shared__ float red[NC][8];
    const __half* y_all = (eid == 2) ? g_y_srm : g_y_hf;
    const __half* Wh    = (eid == 2) ? g_w1srm : g_w1hf;
    float* tout         = (eid == 2) ? g_t_srm : g_t_hf;
    float* psum = g_psum[eid - 2];
    float* psq  = g_psq [eid - 2];

    int pt = blockIdx.x, b = blockIdx.y;
    int px0 = pt * 224;
    int tid = threadIdx.x, warp = tid >> 5, lane = tid & 31;
    int wm = warp >> 2, wn = warp & 3;
    int gid = lane >> 2, tig = lane & 3;
    int Cin = chunks * 16;
    const __half* yb = y_all + (size_t)b * Cin * NHW;

    float acc[2][7][4];
#pragma unroll
    for (int mf = 0; mf < 2; mf++)
#pragma unroll
        for (int nf = 0; nf < 7; nf++)
#pragma unroll
            for (int k = 0; k < 4; k++) acc[mf][nf][k] = 0.f;

    auto stage = [&](int c, int buf) {
#pragma unroll
        for (int k = 0; k < 2; k++) {
            int idx = tid + k * 512;
            if (idx < 448) {
                int i = idx / 28, p = idx % 28;          // ic row, 8-px unit
                cpa16(s2u(Bs[buf] + i * 232 + p * 8),
                      yb + (size_t)(c * 16 + i) * NHW + px0 + p * 8, true);
            } else if (idx < 704) {
                int i2 = idx - 448;
                int oc = i2 >> 1, h = i2 & 1;
                cpa16(s2u(As[buf] + oc * 16 + h * 8),
                      Wh + (size_t)oc * Cin + c * 16 + h * 8, true);
            }
        }
    };

    stage(0, 0); cpa_commit();
    int buf = 0;
    for (int c = 0; c < chunks; c++) {
        if (c + 1 < chunks) { stage(c + 1, buf ^ 1); cpa_commit(); cpa_wait<1>(); }
        else cpa_wait<0>();
        __syncthreads();
        const __half* Asb = As[buf];
        const __half* Bsb = Bs[buf];
        unsigned a[2][4];
#pragma unroll
        for (int mf = 0; mf < 2; mf++) {
            int r = wm * 32 + mf * 16 + gid;
            a[mf][0] = *(const unsigned*)(Asb + r * 16 + tig * 2);
            a[mf][1] = *(const unsigned*)(Asb + (r + 8) * 16 + tig * 2);
            a[mf][2] = *(const unsigned*)(Asb + r * 16 + tig * 2 + 8);
            a[mf][3] = *(const unsigned*)(Asb + (r + 8) * 16 + tig * 2 + 8);
        }
#pragma unroll
        for (int nf = 0; nf < 7; nf++) {
            int px = wn * 56 + nf * 8 + gid;
            __half2 p0, p1;
            p0.x = Bsb[(tig * 2 + 0) * 232 + px];
            p0.y = Bsb[(tig * 2 + 1) * 232 + px];
            p1.x = Bsb[(tig * 2 + 8) * 232 + px];
            p1.y = Bsb[(tig * 2 + 9) * 232 + px];
            unsigned b0 = *(unsigned*)&p0;
            unsigned b1 = *(unsigned*)&p1;
            mma16816(acc[0][nf], a[0], b0, b1);
            mma16816(acc[1][nf], a[1], b0, b1);
        }
        __syncthreads();
        buf ^= 1;
    }

    bool sel = (g_top1[b] == eid);
#pragma unroll
    for (int mf = 0; mf < 2; mf++)
#pragma unroll
        for (int h = 0; h < 2; h++) {
            int oc = wm * 32 + mf * 16 + gid + h * 8;
            float s = 0.f, q = 0.f;
#pragma unroll
            for (int nf = 0; nf < 7; nf++) {
                float v0 = acc[mf][nf][h * 2 + 0], v1 = acc[mf][nf][h * 2 + 1];
                s += v0 + v1; q += v0 * v0 + v1 * v1;
                if (sel) {
                    int px = px0 + wn * 56 + nf * 8 + tig * 2;
                    float2 vv; vv.x = v0; vv.y = v1;
                    *(float2*)(tout + (size_t)(b * NC + oc) * NHW + px) = vv;
                }
            }
            s += __shfl_xor_sync(0xffffffffu, s, 1);
            s += __shfl_xor_sync(0xffffffffu, s, 2);
            q += __shfl_xor_sync(0xffffffffu, q, 1);
            q += __shfl_xor_sync(0xffffffffu, q, 2);
            if (tig == 0) { red[oc][wn] = s; red[oc][4 + wn] = q; }
        }
    __syncthreads();
    if (tid < NC) {
        float ss = red[tid][0] + red[tid][1] + red[tid][2] + red[tid][3];
        float qq = red[tid][4] + red[tid][5] + red[tid][6] + red[tid][7];
        psum[tid * 448 + b * 14 + pt] = ss;
        psq [tid * 448 + b * 14 + pt] = qq;
    }
}

// ---------------- kernel 7: finish BN stats ----------------
__global__ void k_bn(const float* __restrict__ srm_g, const float* __restrict__ srm_b,
                     const float* __restrict__ hf_g,  const float* __restrict__ hf_b) {
    int e = blockIdx.x >> 7, oc = blockIdx.x & 127;
    __shared__ double sm0[64], sm1[64];
    double s = 0.0, q = 0.0;
    for (int i = threadIdx.x; i < 448; i += 64) {
        s += (double)g_psum[e][oc * 448 + i];
        q += (double)g_psq [e][oc * 448 + i];
    }
    sm0[threadIdx.x] = s; sm1[threadIdx.x] = q;
    __syncthreads();
    for (int o = 32; o > 0; o >>= 1) {
        if (threadIdx.x < o) { sm0[threadIdx.x] += sm0[threadIdx.x + o]; sm1[threadIdx.x] += sm1[threadIdx.x + o]; }
        __syncthreads();
    }
    if (threadIdx.x == 0) {
        double N = (double)NB * NHW;
        double mean = sm0[0] / N;
        double var  = sm1[0] / N - mean * mean;
        if (var < 0.0) var = 0.0;
        float gamma = e ? hf_g[oc] : srm_g[oc];
        float beta  = e ? hf_b[oc] : srm_b[oc];
        float scale = gamma * (float)(1.0 / sqrt(var + 1e-5));
        float shift = beta - (float)mean * scale;
        g_bnp[e][oc] = make_float2(scale, shift);
    }
}

// ---------------- kernel 8: routed main conv via mma, all-taps A staging ----------------
// Dynamic smem: A = K2*128oc*16ic (single buffer), B = 2 x RIN*CIN*16.
// 2 syncs per ic-chunk instead of 2 per tap.
constexpr int CONV_DYN = 25 * 2048 * 2 + 2 * 8 * 60 * 16 * 2;   // 133120 B (K=5 worst case)

template<int K>
__device__ void conv_mma(const __half* __restrict__ Wh, int b, int r0,
                         float acc[2][7][4], __half* dyn, int warp, int lane) {
    const int PAD = K / 2;
    const int RIN = 4 + K - 1;
    const int CIN = 56 + K - 1;
    const int K2 = K * K;
    __half* As  = dyn;
    __half* Bs0 = dyn + K2 * 2048;
    __half* Bs1 = Bs0 + RIN * CIN * 16;
    int tid = threadIdx.x;
    const __half* xb = g_xh + (size_t)b * NHW * NC;

    auto stageB = [&](int chunk, __half* Bb) {
        int ic0 = chunk * 16;
        int tot = RIN * CIN * 2;
        for (int idx = tid; idx < tot; idx += 512) {
            int hsel = idx & 1, i2 = idx >> 1;
            int i = i2 / CIN, j = i2 % CIN;
            int xr = r0 + i - PAD, xc = j - PAD;
            bool ok = (xr >= 0 && xr < NH && xc >= 0 && xc < NWW);
            int xrc = xr < 0 ? 0 : (xr > 55 ? 55 : xr);
            int xcc = xc < 0 ? 0 : (xc > 55 ? 55 : xc);
            const __half* src = xb + ((size_t)(xrc * 56 + xcc)) * NC + ic0 + hsel * 8;
            cpa16(s2u(Bb + (i * CIN + j) * 16 + hsel * 8), src, ok);
        }
    };
    auto stageA_all = [&](int chunk) {
        int ic0 = chunk * 16;
        for (int u = tid; u < K2 * 256; u += 512) {
            int t = u >> 8, r2 = u & 255;
            int oc = r2 >> 1, h = r2 & 1;
            cpa16(s2u(As + t * 2048 + oc * 16 + h * 8),
                  Wh + ((size_t)t * NC + oc) * NC + ic0 + h * 8, true);
        }
    };

    int gid = lane >> 2, tig = lane & 3;
    int oc0 = (warp >> 2) * 32, rr = warp & 3;

    stageB(0, Bs0); cpa_commit();
    int bbuf = 0;
    for (int c = 0; c < 8; c++) {
        stageA_all(c); cpa_commit();
        bool pre = (c + 1 < 8);
        if (pre) { stageB(c + 1, bbuf ? Bs0 : Bs1); cpa_commit(); cpa_wait<1>(); }
        else cpa_wait<0>();
        __syncthreads();
        const __half* Bs = bbuf ? Bs1 : Bs0;
#pragma unroll
        for (int t = 0; t < K2; t++) {
            const __half* At = As + t * 2048;
            int dy = t / K, dx = t % K;
            unsigned a[2][4];
#pragma unroll
            for (int mf = 0; mf < 2; mf++) {
                int r = oc0 + mf * 16 + gid;
                a[mf][0] = *(const unsigned*)(At + r * 16 + tig * 2);
                a[mf][1] = *(const unsigned*)(At + (r + 8) * 16 + tig * 2);
                a[mf][2] = *(const unsigned*)(At + r * 16 + tig * 2 + 8);
                a[mf][3] = *(const unsigned*)(At + (r + 8) * 16 + tig * 2 + 8);
            }
            int rowi = rr + dy;
#pragma unroll
            for (int nf = 0; nf < 7; nf++) {
                const __half* bp = Bs + ((rowi * CIN) + nf * 8 + gid + dx) * 16 + tig * 2;
                unsigned b0 = *(const unsigned*)bp;
                unsigned b1 = *(const unsigned*)(bp + 8);
                mma16816(acc[0][nf], a[0], b0, b1);
                mma16816(acc[1][nf], a[1], b0, b1);
            }
        }
        __syncthreads();
        bbuf ^= 1;
    }
}

__global__ __launch_bounds__(512, 1) void k_out_mma(float* __restrict__ out) {
    extern __shared__ __align__(16) __half dyn[];
    int rt = blockIdx.x, b = blockIdx.y;
    int r0 = rt * 4;
    int e = g_top1[b];
    int warp = threadIdx.x >> 5, lane = threadIdx.x & 31;
    float acc[2][7][4];
#pragma unroll
    for (int mf = 0; mf < 2; mf++)
#pragma unroll
        for (int nf = 0; nf < 7; nf++)
#pragma unroll
            for (int k = 0; k < 4; k++) acc[mf][nf][k] = 0.f;

    if (e == 1)
        conv_mma<5>(g_wh5, b, r0, acc, dyn, warp, lane);
    else
        conv_mma<3>(e == 0 ? g_wh3cd : g_wh3sh, b, r0, acc, dyn, warp, lane);

    int gid = lane >> 2, tig = lane & 3;
    int oc0 = (warp >> 2) * 32, rr = warp & 3;
    int row = r0 + rr;
    const float* tbase = (e == 2) ? g_t_srm : g_t_hf;
#pragma unroll
    for (int mf = 0; mf < 2; mf++)
#pragma unroll
        for (int nf = 0; nf < 7; nf++)
#pragma unroll
            for (int h = 0; h < 2; h++) {
                int oc = oc0 + mf * 16 + gid + h * 8;
                int c = nf * 8 + tig * 2;
                float v0 = acc[mf][nf][h * 2 + 0], v1 = acc[mf][nf][h * 2 + 1];
                size_t off = (size_t)(b * NC + oc) * NHW + row * 56 + c;
                if (e >= 2) {
                    float2 bnp2 = g_bnp[e - 2][oc];
                    float2 tv = *(const float2*)(tbase + off);
                    v0 += fmaxf(tv.x * bnp2.x + bnp2.y, 0.f);
                    v1 += fmaxf(tv.y * bnp2.x + bnp2.y, 0.f);
                }
                float2 vv; vv.x = v0; vv.y = v1;
                *(float2*)(out + off) = vv;
            }
}

// ---------------- launcher ----------------
extern "C" void kernel_launch(void* const* d_in, const int* in_sizes, int n_in,
                              void* d_out, int out_size) {
    const float* x      = (const float*)d_in[0];
    const float* Wg     = (const float*)d_in[1];
    const float* cd_w   = (const float*)d_in[2];
    const float* bayar  = (const float*)d_in[3];
    const float* srm_k  = (const float*)d_in[4];
    const float* srm_ow = (const float*)d_in[5];
    const float* srm_g  = (const float*)d_in[6];
    const float* srm_b  = (const float*)d_in[7];
    const float* hf_k   = (const float*)d_in[8];
    const float* hf_ow  = (const float*)d_in[9];
    const float* hf_g   = (const float*)d_in[10];
    const float* hf_b   = (const float*)d_in[11];
    const float* shw    = (const float*)d_in[12];
    float* out = (float*)d_out;

    // idempotent; called every time (no static guards allowed)
    cudaFuncSetAttribute(k_out_mma, cudaFuncAttributeMaxDynamicSharedMemorySize, CONV_DYN);

    k_prep<<<(NC * NC + 127) / 128, 128>>>(cd_w, bayar, shw, srm_ow, hf_ow);
    k_xh<<<dim3(56, NB), 256>>>(x);
    k_pool<<<NB * NC, 128>>>(x);
    k_gate<<<1, 128>>>(Wg, out);
    k_dw_srm<<<NB * NC, 256>>>(x, srm_k);
    k_dw_hf<<<NB * NC, 256>>>(x, hf_k);
    k_c1x1_mma<<<dim3(14, NB), 512>>>(24, 2);
    k_c1x1_mma<<<dim3(14, NB), 512>>>(8, 3);
    k_bn<<<256, 64>>>(srm_g, srm_b, hf_g, hf_b);
    k_out_mma<<<dim3(14, NB), 512, CONV_DYN>>>(out);
}